// round 11
// baseline (speedup 1.0000x reference)
#include <cuda_runtime.h>
#include <cuda_fp16.h>
#include <cstdint>
#include <cstddef>

#define BB 4
#define HH 12
#define SS 2048
#define DD 64
#define EE 768
#define MM (BB*SS)
#define NT (BB*HH*SS*DD)   // 6291456

// ---------------- scratch (__device__ globals; no allocation) --------------
__device__ __half g_xhi[MM*EE], g_xlo[MM*EE];
__device__ __half g_wThi[4*EE*EE], g_wTlo[4*EE*EE];
__device__ __half g_qhi[NT];
__device__ __half g_khi[NT];
__device__ __half g_vthi[NT];              // V transposed: [bh][d][s] (hi only)
__device__ __half g_ohi[NT], g_olo[NT];

#define LOG2E 1.4426950408889634f

__constant__ float c_slopes[HH] = {
    0.6299605249f, 0.396850263f, 0.25f, 0.1574901312f,
    0.0992125657f, 0.0625f, 0.0393725328f, 0.0248031414f,
    0.015625f, 0.0098431332f, 0.0062007854f, 0.00390625f};

// ---------------------------------------------------------------------------
__device__ __forceinline__ uint32_t smem_u32(const void* p) {
    uint32_t a;
    asm("{ .reg .u64 t; cvta.to.shared.u64 t, %1; cvt.u32.u64 %0, t; }"
        : "=r"(a) : "l"(p));
    return a;
}
__device__ __forceinline__ unsigned h2u(__half2 h) {
    return reinterpret_cast<unsigned&>(h);
}
__device__ __forceinline__ void fsplit2(float a, float b, unsigned& hi, unsigned& lo) {
    __half2 h = __floats2half2_rn(a, b);
    float2 hf = __half22float2(h);
    __half2 l = __floats2half2_rn(a - hf.x, b - hf.y);
    hi = h2u(h); lo = h2u(l);
}
__device__ __forceinline__ float ex2(float x) {
    float y;
    asm("ex2.approx.f32 %0, %1;" : "=f"(y) : "f"(x));
    return y;
}
__device__ __forceinline__ void mma16(float* d, const unsigned* a,
                                      unsigned b0, unsigned b1) {
    asm volatile(
        "mma.sync.aligned.m16n8k16.row.col.f32.f16.f16.f32 "
        "{%0,%1,%2,%3}, {%4,%5,%6,%7}, {%8,%9}, {%0,%1,%2,%3};"
        : "+f"(d[0]), "+f"(d[1]), "+f"(d[2]), "+f"(d[3])
        : "r"(a[0]), "r"(a[1]), "r"(a[2]), "r"(a[3]), "r"(b0), "r"(b1));
}
__device__ __forceinline__ void ldsm4(unsigned& r0, unsigned& r1,
                                      unsigned& r2, unsigned& r3, uint32_t a) {
    asm volatile("ldmatrix.sync.aligned.m8n8.x4.shared.b16 {%0,%1,%2,%3}, [%4];"
                 : "=r"(r0), "=r"(r1), "=r"(r2), "=r"(r3) : "r"(a));
}
__device__ __forceinline__ void cpa16(uint32_t dst, const void* src) {
    asm volatile("cp.async.cg.shared.global [%0], [%1], 16;"
                 :: "r"(dst), "l"(src));
}
__device__ __forceinline__ void cpcommit() {
    asm volatile("cp.async.commit_group;" ::: "memory");
}
template <int N>
__device__ __forceinline__ void cpwait() {
    asm volatile("cp.async.wait_group %0;" :: "n"(N) : "memory");
}

// ---------------------------------------------------------------------------
// prepass: split fp32 -> fp16 hi/lo
// ---------------------------------------------------------------------------
__global__ void __launch_bounds__(256)
split_vec(const float* __restrict__ in, __half* __restrict__ hi,
          __half* __restrict__ lo, int n4) {
    int i = blockIdx.x * 256 + threadIdx.x;
    if (i >= n4) return;
    float4 f = ((const float4*)in)[i];
    __half2 h0 = __floats2half2_rn(f.x, f.y);
    __half2 h1 = __floats2half2_rn(f.z, f.w);
    float2 a = __half22float2(h0), b = __half22float2(h1);
    __half2 l0 = __floats2half2_rn(f.x - a.x, f.y - a.y);
    __half2 l1 = __floats2half2_rn(f.z - b.x, f.w - b.y);
    ((__half2*)hi)[2*i]   = h0; ((__half2*)hi)[2*i+1] = h1;
    ((__half2*)lo)[2*i]   = l0; ((__half2*)lo)[2*i+1] = l1;
}

__global__ void __launch_bounds__(256)
split_wT(const float* __restrict__ W, __half* __restrict__ hiT,
         __half* __restrict__ loT) {
    __shared__ float t[32][33];
    const int r0 = blockIdx.y * 32, c0 = blockIdx.x * 32;
    const int tx = threadIdx.x, ty = threadIdx.y;   // 32 x 8
#pragma unroll
    for (int j = 0; j < 4; j++)
        t[ty + 8*j][tx] = W[(size_t)(r0 + ty + 8*j) * EE + c0 + tx];
    __syncthreads();
#pragma unroll
    for (int j = 0; j < 4; j++) {
        float f = t[tx][ty + 8*j];     // = W[r0+tx][c0+ty+8j]
        __half h = __float2half_rn(f);
        size_t o = (size_t)(c0 + ty + 8*j) * EE + r0 + tx;
        hiT[o] = h;
        loT[o] = __float2half_rn(f - __half2float(h));
    }
}

// ---------------------------------------------------------------------------
// fp16x2 GEMM v4 (unchanged from R10): tile 128x128, 8 warps, BK=32,
// 2-stage cp.async. STREAMS: 3 = compensated; 1 = hi*hi only.
// MODE: 0=float out+bias; 1=Q (scale 0.125*log2e, fp16 hi out);
//       2=K (fp16 hi out); 3=V (fp16 hi, transposed [bh][d][s]).
// ---------------------------------------------------------------------------
#define G_SMEM 81920

template <int MODE, int STREAMS>
__global__ void __launch_bounds__(256)
gemm16(const __half* __restrict__ Ah, const __half* __restrict__ Al,
       const __half* __restrict__ Bh, const __half* __restrict__ Bl,
       const float* __restrict__ bias, float* __restrict__ outf,
       __half* __restrict__ ohi, __half* __restrict__ olo) {
    extern __shared__ __half sm[];

    const int tid  = threadIdx.x;
    const int lane = tid & 31;
    const int warp = tid >> 5;
    const int wm   = (warp >> 1) * 32;     // 0..96
    const int wn   = (warp & 1) * 64;      // 0 or 64
    const int m0   = blockIdx.x * 128;
    const int n0   = blockIdx.y * 128;
    const uint32_t smb = smem_u32(sm);

    const int lrow = (lane & 7) + ((lane & 16) >> 1);
    const int lcol = (lane & 8);

    float acc[2][8][4];
#pragma unroll
    for (int mf = 0; mf < 2; mf++)
#pragma unroll
        for (int nf = 0; nf < 8; nf++)
#pragma unroll
            for (int i = 0; i < 4; i++) acc[mf][nf][i] = 0.f;

    auto load_stage = [&](int st, int k0) {
        if (STREAMS == 3) {
#pragma unroll
            for (int i = 0; i < 8; i++) {
                const int u = tid + i * 256;      // 0..2047
                const int t = u >> 9;              // 0=Ah 1=Al 2=Bh 3=Bl
                const int w = u & 511;
                const int row = w >> 2, c8 = (w & 3) * 8;
                const __half* src;
                if (t == 0)      src = Ah + (size_t)(m0 + row) * EE + k0 + c8;
                else if (t == 1) src = Al + (size_t)(m0 + row) * EE + k0 + c8;
                else if (t == 2) src = Bh + (size_t)(n0 + row) * EE + k0 + c8;
                else             src = Bl + (size_t)(n0 + row) * EE + k0 + c8;
                const uint32_t dsth = st * 20480 + t * 5120 + row * 40 + c8;
                cpa16(smb + dsth * 2, src);
            }
        } else {
#pragma unroll
            for (int i = 0; i < 4; i++) {
                const int u = tid + i * 256;      // 0..1023
                const int t = u >> 9;              // 0=Ah 1=Bh
                const int w = u & 511;
                const int row = w >> 2, c8 = (w & 3) * 8;
                const __half* src = t ? Bh + (size_t)(n0 + row) * EE + k0 + c8
                                      : Ah + (size_t)(m0 + row) * EE + k0 + c8;
                const uint32_t dsth = st * 20480 + t * 10240 + row * 40 + c8;
                cpa16(smb + dsth * 2, src);
            }
        }
        cpcommit();
    };

    load_stage(0, 0);
    const int NC = EE / 32;   // 24
    for (int c = 0; c < NC; c++) {
        const int st = c & 1;
        if (c + 1 < NC) { load_stage(st ^ 1, (c + 1) * 32); cpwait<1>(); }
        else            { cpwait<0>(); }
        __syncthreads();

        const uint32_t aH = smb + (st * 20480) * 2;
        const uint32_t aL = aH + 5120 * 2;
        const uint32_t bH = smb + (st * 20480 + 10240) * 2;
        const uint32_t bL = bH + 5120 * 2;

#pragma unroll
        for (int kk = 0; kk < 2; kk++) {
            const int cc = kk * 16;
            unsigned a_h[2][4], a_l[2][4];
#pragma unroll
            for (int mf = 0; mf < 2; mf++) {
                const int ar = wm + mf * 16 + (lane & 15);
                const int ac = cc + ((lane & 16) >> 1);
                ldsm4(a_h[mf][0], a_h[mf][1], a_h[mf][2], a_h[mf][3],
                      aH + (ar * 40 + ac) * 2);
                if (STREAMS == 3)
                    ldsm4(a_l[mf][0], a_l[mf][1], a_l[mf][2], a_l[mf][3],
                          aL + (ar * 40 + ac) * 2);
            }
#pragma unroll
            for (int p = 0; p < 4; p++) {
                const int br = wn + p * 16 + lrow;
                const int bc = cc + lcol;
                unsigned bh[4], bl[4];
                ldsm4(bh[0], bh[1], bh[2], bh[3], bH + (br * 40 + bc) * 2);
                if (STREAMS == 3)
                    ldsm4(bl[0], bl[1], bl[2], bl[3], bL + (br * 40 + bc) * 2);
#pragma unroll
                for (int q = 0; q < 2; q++) {
                    const int nf = 2 * p + q;
                    mma16(acc[0][nf], a_h[0], bh[2*q], bh[2*q+1]);
                    mma16(acc[1][nf], a_h[1], bh[2*q], bh[2*q+1]);
                    if (STREAMS == 3) {
                        mma16(acc[0][nf], a_h[0], bl[2*q], bl[2*q+1]);
                        mma16(acc[1][nf], a_h[1], bl[2*q], bl[2*q+1]);
                        mma16(acc[0][nf], a_l[0], bh[2*q], bh[2*q+1]);
                        mma16(acc[1][nf], a_l[1], bh[2*q], bh[2*q+1]);
                    }
                }
            }
        }
        __syncthreads();
    }

    // Epilogue: C layout r = g(+8), c = 2*t4(+1)
    const int g  = lane >> 2;
    const int t4 = lane & 3;
#pragma unroll
    for (int nf = 0; nf < 8; nf++) {
        const int nl = wn + nf * 8 + 2 * t4;       // 0..127 (even)
        const int n  = n0 + nl;
        const int hh_ = n >> 6;                    // head for MODE 1/2/3
        const int dl  = nl & 63;
        const float b0 = bias[n], b1 = bias[n + 1];
#pragma unroll
        for (int mf = 0; mf < 2; mf++) {
            const int m_lo = m0 + wm + mf * 16 + g;
            const int m_hi = m_lo + 8;
            float v0 = acc[mf][nf][0] + b0, v1 = acc[mf][nf][1] + b1;
            float v2 = acc[mf][nf][2] + b0, v3 = acc[mf][nf][3] + b1;
            if (MODE == 0) {
                *(float2*)(outf + (size_t)m_lo * EE + n) = make_float2(v0, v1);
                *(float2*)(outf + (size_t)m_hi * EE + n) = make_float2(v2, v3);
            } else if (MODE == 1 || MODE == 2) {
                if (MODE == 1) {
                    const float qs = 0.125f * LOG2E;
                    v0 *= qs; v1 *= qs; v2 *= qs; v3 *= qs;
                }
                const int b_lo = m_lo >> 11, s_lo = m_lo & (SS - 1);
                const int b_hi = m_hi >> 11, s_hi = m_hi & (SS - 1);
                size_t o_lo = (((size_t)(b_lo * HH + hh_)) * SS + s_lo) * DD + dl;
                size_t o_hi = (((size_t)(b_hi * HH + hh_)) * SS + s_hi) * DD + dl;
                *(unsigned*)(ohi + o_lo) = h2u(__floats2half2_rn(v0, v1));
                *(unsigned*)(ohi + o_hi) = h2u(__floats2half2_rn(v2, v3));
            } else {  // MODE 3: V (hi only) transposed [bh][d][s]
                const int b_lo = m_lo >> 11, s_lo = m_lo & (SS - 1);
                const int b_hi = m_hi >> 11, s_hi = m_hi & (SS - 1);
                const size_t base_lo = ((size_t)(b_lo * HH + hh_)) * DD * SS;
                const size_t base_hi = ((size_t)(b_hi * HH + hh_)) * DD * SS;
                float vs[4] = {v0, v1, v2, v3};
#pragma unroll
                for (int e = 0; e < 4; e++) {
                    const int d = dl + (e & 1);
                    const size_t o = (e < 2 ? base_lo : base_hi) +
                                     (size_t)d * SS + (e < 2 ? s_lo : s_hi);
                    ohi[o] = __float2half_rn(vs[e]);
                }
            }
        }
    }
}

// ---------------------------------------------------------------------------
// Flash attention v6: qtile 128 (8 warps / 256 thr), ktile 64 double-buffered.
// Per-warp diagonal guard: warp base = q0+warp*16; its last live tile is
// kt == base>>6 (the only edge tile); later tiles fully masked -> skipped.
// Q/K/V fp16 hi-only, log2-domain, fp16x2 exp, ones-MMA rowsum,
// ALiBi window slope2*k <= 36.
// smem kv[2 stages][2 arrays (Kh,Vt)][64*72] = 36864 B.
// ---------------------------------------------------------------------------
__global__ void __launch_bounds__(256)
attn16(const __half* __restrict__ Qh, const __half* __restrict__ Kh,
       const __half* __restrict__ Vth,
       __half* __restrict__ Ohi, __half* __restrict__ Olo) {
    __shared__ __half kv[2][2][64*72];

    const int tid  = threadIdx.x;
    const int lane = tid & 31;
    const int warp = tid >> 5;            // 0..7
    const int g    = lane >> 2;
    const int t4   = lane & 3;
    const uint32_t smb = smem_u32(kv);

    const int lrow = (lane & 7) + ((lane & 16) >> 1);
    const int lcol = (lane & 8);

    const int bh = blockIdx.y;
    const int h  = bh % HH;
    const int q0 = blockIdx.x * 128;
    const float slope2 = c_slopes[h] * LOG2E;

    const __half* Qhb = Qh + (size_t)bh * SS * DD;
    const __half* Khb = Kh + (size_t)bh * SS * DD;
    const __half* Vhb = Vth + (size_t)bh * DD * SS;

    const int base = q0 + warp * 16;      // warp's first q row
    const int r0   = base + g;
    const int ktW  = base >> 6;           // warp's last live (edge) tile

    unsigned qh[4][4];
#pragma unroll
    for (int kk = 0; kk < 4; kk++) {
        const int c = kk * 16 + 2 * t4;
        qh[kk][0] = *(const unsigned*)(Qhb + (size_t)r0 * DD + c);
        qh[kk][1] = *(const unsigned*)(Qhb + (size_t)(r0 + 8) * DD + c);
        qh[kk][2] = *(const unsigned*)(Qhb + (size_t)r0 * DD + c + 8);
        qh[kk][3] = *(const unsigned*)(Qhb + (size_t)(r0 + 8) * DD + c + 8);
    }

    float Oacc[8][4];
#pragma unroll
    for (int i = 0; i < 8; i++)
#pragma unroll
        for (int j = 0; j < 4; j++) Oacc[i][j] = 0.f;
    float mrow0 = -1e30f, mrow1 = -1e30f, lrow0f = 0.f, lrow1f = 0.f;

    // CTA loop bound: max over warps of ktW, clipped by ALiBi window.
    int ktEnd = (q0 + 112) >> 6;
    {
        const int ctile = ((int)(36.f / slope2)) >> 6;
        if (ctile < ktEnd) ktEnd = ctile;
    }

    auto load_kv = [&](int st, int k0) {
#pragma unroll
        for (int i = 0; i < 4; i++) {
            const int u = tid + i * 256;       // 0..1023
            const int t = u >> 9;              // 0=K, 1=Vt
            const int w = u & 511;
            const int r = w >> 3, c8 = (w & 7) * 8;
            const __half* src = t ? (Vhb + (size_t)r * SS + k0 + c8)
                                  : (Khb + (size_t)(k0 + r) * DD + c8);
            const uint32_t dst = smb + (((st * 2 + t) * 4608) + r * 72 + c8) * 2;
            cpa16(dst, src);
        }
        cpcommit();
    };

    load_kv(0, 0);
    for (int kt = 0; kt <= ktEnd; kt++) {
        const int k0 = kt * 64;
        const int st = kt & 1;
        if (kt < ktEnd) { load_kv(st ^ 1, k0 + 64); cpwait<1>(); }
        else            { cpwait<0>(); }
        __syncthreads();

        if (kt <= ktW) {   // warp-level: tiles past the diagonal are all-masked
            const uint32_t ksh = smb + (st * 2) * 4608 * 2;
            const uint32_t vth = smb + (st * 2 + 1) * 4608 * 2;

            float S[8][4];
#pragma unroll
            for (int j = 0; j < 8; j++)
#pragma unroll
                for (int i = 0; i < 4; i++) S[j][i] = 0.f;
#pragma unroll
            for (int kk = 0; kk < 4; kk++) {
                const int cc = kk * 16 + lcol;
#pragma unroll
                for (int jp = 0; jp < 4; jp++) {
                    const int br = jp * 16 + lrow;
                    unsigned bh_[4];
                    ldsm4(bh_[0], bh_[1], bh_[2], bh_[3], ksh + (br * 72 + cc) * 2);
                    mma16(S[2*jp],     qh[kk], bh_[0], bh_[1]);
                    mma16(S[2*jp + 1], qh[kk], bh_[2], bh_[3]);
                }
            }

            // ALiBi (-slope2*k; row term cancels in softmax) + causal mask
            const bool edge = (kt == ktW);
            float tm0 = -1e30f, tm1 = -1e30f;
#pragma unroll
            for (int j = 0; j < 8; j++) {
                const int kc0 = k0 + j * 8 + 2 * t4;
                const float c0 = -slope2 * (float)kc0;
                const float c1 = c0 - slope2;
                S[j][0] += c0;
                S[j][1] += c1;
                S[j][2] += c0;
                S[j][3] += c1;
                if (edge) {
                    if (kc0 > r0)         S[j][0] = -1e30f;
                    if (kc0 + 1 > r0)     S[j][1] = -1e30f;
                    if (kc0 > r0 + 8)     S[j][2] = -1e30f;
                    if (kc0 + 1 > r0 + 8) S[j][3] = -1e30f;
                }
                tm0 = fmaxf(tm0, fmaxf(S[j][0], S[j][1]));
                tm1 = fmaxf(tm1, fmaxf(S[j][2], S[j][3]));
            }
            tm0 = fmaxf(tm0, __shfl_xor_sync(0xffffffffu, tm0, 1));
            tm0 = fmaxf(tm0, __shfl_xor_sync(0xffffffffu, tm0, 2));
            tm1 = fmaxf(tm1, __shfl_xor_sync(0xffffffffu, tm1, 1));
            tm1 = fmaxf(tm1, __shfl_xor_sync(0xffffffffu, tm1, 2));

            const float mn0 = fmaxf(mrow0, tm0);
            const float mn1 = fmaxf(mrow1, tm1);
            const float al0 = ex2(mrow0 - mn0);
            const float al1 = ex2(mrow1 - mn1);
            mrow0 = mn0; mrow1 = mn1;
#pragma unroll
            for (int i = 0; i < 8; i++) {
                Oacc[i][0] *= al0; Oacc[i][1] *= al0;
                Oacc[i][2] *= al1; Oacc[i][3] *= al1;
            }

            // P = 2^(S - m) fp16 pairs (A-frag layout); rowsum via ones-MMA.
            float Lacc[4] = {0.f, 0.f, 0.f, 0.f};
#pragma unroll
            for (int jj = 0; jj < 4; jj++) {
                unsigned ph[4];
                ph[0] = h2u(h2exp2(__floats2half2_rn(S[2*jj][0] - mn0, S[2*jj][1] - mn0)));
                ph[1] = h2u(h2exp2(__floats2half2_rn(S[2*jj][2] - mn1, S[2*jj][3] - mn1)));
                ph[2] = h2u(h2exp2(__floats2half2_rn(S[2*jj+1][0] - mn0, S[2*jj+1][1] - mn0)));
                ph[3] = h2u(h2exp2(__floats2half2_rn(S[2*jj+1][2] - mn1, S[2*jj+1][3] - mn1)));
                mma16(Lacc, ph, 0x3C003C00u, 0x3C003C00u);   // rowsum
                const int cc = jj * 16 + lcol;
#pragma unroll
                for (int dp = 0; dp < 4; dp++) {
                    const int d0 = 2 * dp, d1 = d0 + 1;
                    const int vr = dp * 16 + lrow;
                    unsigned vh[4];
                    ldsm4(vh[0], vh[1], vh[2], vh[3], vth + (vr * 72 + cc) * 2);
                    mma16(Oacc[d0], ph, vh[0], vh[1]);
                    mma16(Oacc[d1], ph, vh[2], vh[3]);
                }
            }
            lrow0f = lrow0f * al0 + Lacc[0];
            lrow1f = lrow1f * al1 + Lacc[2];
        }
        __syncthreads();
    }

    const float inv0 = 1.f / lrow0f;
    const float inv1 = 1.f / lrow1f;
    __half* OhB = Ohi + (size_t)bh * SS * DD;
    __half* OlB = Olo + (size_t)bh * SS * DD;
#pragma unroll
    for (int dn = 0; dn < 8; dn++) {
        const int col = dn * 8 + 2 * t4;
        unsigned hh, ll;
        fsplit2(Oacc[dn][0] * inv0, Oacc[dn][1] * inv0, hh, ll);
        *(unsigned*)(OhB + (size_t)r0 * DD + col) = hh;
        *(unsigned*)(OlB + (size_t)r0 * DD + col) = ll;
        fsplit2(Oacc[dn][2] * inv1, Oacc[dn][3] * inv1, hh, ll);
        *(unsigned*)(OhB + (size_t)(r0 + 8) * DD + col) = hh;
        *(unsigned*)(OlB + (size_t)(r0 + 8) * DD + col) = ll;
    }
}

// ---------------------------------------------------------------------------
extern "C" void kernel_launch(void* const* d_in, const int* in_sizes, int n_in,
                              void* d_out, int out_size) {
    const float* x  = (const float*)d_in[0];
    const float* Wq = (const float*)d_in[1];
    const float* bq = (const float*)d_in[2];
    const float* Wk = (const float*)d_in[3];
    const float* bk = (const float*)d_in[4];
    const float* Wv = (const float*)d_in[5];
    const float* bv = (const float*)d_in[6];
    const float* Wo = (const float*)d_in[7];
    const float* bo = (const float*)d_in[8];
    float* out = (float*)d_out;

    __half *xhi, *xlo, *wThi, *wTlo, *qhi, *khi, *vthi, *ohi, *olo;
    cudaGetSymbolAddress((void**)&xhi, g_xhi);
    cudaGetSymbolAddress((void**)&xlo, g_xlo);
    cudaGetSymbolAddress((void**)&wThi, g_wThi);
    cudaGetSymbolAddress((void**)&wTlo, g_wTlo);
    cudaGetSymbolAddress((void**)&qhi, g_qhi);
    cudaGetSymbolAddress((void**)&khi, g_khi);
    cudaGetSymbolAddress((void**)&vthi, g_vthi);
    cudaGetSymbolAddress((void**)&ohi, g_ohi);
    cudaGetSymbolAddress((void**)&olo, g_olo);

    cudaFuncSetAttribute(gemm16<0,3>, cudaFuncAttributeMaxDynamicSharedMemorySize, G_SMEM);
    cudaFuncSetAttribute(gemm16<1,1>, cudaFuncAttributeMaxDynamicSharedMemorySize, G_SMEM);
    cudaFuncSetAttribute(gemm16<2,1>, cudaFuncAttributeMaxDynamicSharedMemorySize, G_SMEM);
    cudaFuncSetAttribute(gemm16<3,3>, cudaFuncAttributeMaxDynamicSharedMemorySize, G_SMEM);

    // prepass
    const int n4 = MM * EE / 4;
    split_vec<<<(n4 + 255) / 256, 256>>>(x, xhi, xlo, n4);
    dim3 wt(24, 24), wb(32, 8);
    split_wT<<<wt, wb>>>(Wq, wThi + 0 * EE * EE, wTlo + 0 * EE * EE);
    split_wT<<<wt, wb>>>(Wk, wThi + 1 * EE * EE, wTlo + 1 * EE * EE);
    split_wT<<<wt, wb>>>(Wv, wThi + 2 * EE * EE, wTlo + 2 * EE * EE);
    split_wT<<<wt, wb>>>(Wo, wThi + 3 * EE * EE, wTlo + 3 * EE * EE);

    dim3 gg(MM / 128, EE / 128);   // 64 x 6
    gemm16<1,1><<<gg, 256, G_SMEM>>>(xhi, nullptr, wThi + 0 * EE * EE, nullptr,
                                     bq, nullptr, qhi, nullptr);
    gemm16<2,1><<<gg, 256, G_SMEM>>>(xhi, nullptr, wThi + 1 * EE * EE, nullptr,
                                     bk, nullptr, khi, nullptr);
    gemm16<3,3><<<gg, 256, G_SMEM>>>(xhi, xlo, wThi + 2 * EE * EE, wTlo + 2 * EE * EE,
                                     bv, nullptr, vthi, nullptr);

    dim3 ga(SS / 128, BB * HH);   // 16 x 48
    attn16<<<ga, 256>>>(qhi, khi, vthi, ohi, olo);

    // [B,H,S,D] flat == [B*S, E] (reference's head-major flatten)
    gemm16<0,3><<<gg, 256, G_SMEM>>>(ohi, olo, wThi + 3 * EE * EE, wTlo + 3 * EE * EE,
                                     bo, out, nullptr, nullptr);
}

// round 12
// speedup vs baseline: 1.0761x; 1.0761x over previous
#include <cuda_runtime.h>
#include <cuda_fp16.h>
#include <cstdint>
#include <cstddef>

#define BB 4
#define HH 12
#define SS 2048
#define DD 64
#define EE 768
#define MM (BB*SS)
#define NT (BB*HH*SS*DD)   // 6291456

// ---------------- scratch (__device__ globals; no allocation) --------------
__device__ __half g_xhi[MM*EE], g_xlo[MM*EE];
__device__ __half g_wThi[4*EE*EE], g_wTlo[4*EE*EE];
__device__ __half g_qhi[NT];
__device__ __half g_khi[NT];
__device__ __half g_vthi[NT];              // V transposed: [bh][d][s] (hi only)
__device__ __half g_ohi[NT], g_olo[NT];

#define LOG2E 1.4426950408889634f

__constant__ float c_slopes[HH] = {
    0.6299605249f, 0.396850263f, 0.25f, 0.1574901312f,
    0.0992125657f, 0.0625f, 0.0393725328f, 0.0248031414f,
    0.015625f, 0.0098431332f, 0.0062007854f, 0.00390625f};

// ---------------------------------------------------------------------------
__device__ __forceinline__ uint32_t smem_u32(const void* p) {
    uint32_t a;
    asm("{ .reg .u64 t; cvta.to.shared.u64 t, %1; cvt.u32.u64 %0, t; }"
        : "=r"(a) : "l"(p));
    return a;
}
__device__ __forceinline__ unsigned h2u(__half2 h) {
    return reinterpret_cast<unsigned&>(h);
}
__device__ __forceinline__ void fsplit2(float a, float b, unsigned& hi, unsigned& lo) {
    __half2 h = __floats2half2_rn(a, b);
    float2 hf = __half22float2(h);
    __half2 l = __floats2half2_rn(a - hf.x, b - hf.y);
    hi = h2u(h); lo = h2u(l);
}
__device__ __forceinline__ float ex2(float x) {
    float y;
    asm("ex2.approx.f32 %0, %1;" : "=f"(y) : "f"(x));
    return y;
}
__device__ __forceinline__ void mma16(float* d, const unsigned* a,
                                      unsigned b0, unsigned b1) {
    asm volatile(
        "mma.sync.aligned.m16n8k16.row.col.f32.f16.f16.f32 "
        "{%0,%1,%2,%3}, {%4,%5,%6,%7}, {%8,%9}, {%0,%1,%2,%3};"
        : "+f"(d[0]), "+f"(d[1]), "+f"(d[2]), "+f"(d[3])
        : "r"(a[0]), "r"(a[1]), "r"(a[2]), "r"(a[3]), "r"(b0), "r"(b1));
}
__device__ __forceinline__ void ldsm4(unsigned& r0, unsigned& r1,
                                      unsigned& r2, unsigned& r3, uint32_t a) {
    asm volatile("ldmatrix.sync.aligned.m8n8.x4.shared.b16 {%0,%1,%2,%3}, [%4];"
                 : "=r"(r0), "=r"(r1), "=r"(r2), "=r"(r3) : "r"(a));
}
__device__ __forceinline__ void cpa16(uint32_t dst, const void* src) {
    asm volatile("cp.async.cg.shared.global [%0], [%1], 16;"
                 :: "r"(dst), "l"(src));
}
__device__ __forceinline__ void cpcommit() {
    asm volatile("cp.async.commit_group;" ::: "memory");
}
template <int N>
__device__ __forceinline__ void cpwait() {
    asm volatile("cp.async.wait_group %0;" :: "n"(N) : "memory");
}

// ---------------------------------------------------------------------------
// prepass: split fp32 -> fp16 hi/lo
// ---------------------------------------------------------------------------
__global__ void __launch_bounds__(256)
split_vec(const float* __restrict__ in, __half* __restrict__ hi,
          __half* __restrict__ lo, int n4) {
    int i = blockIdx.x * 256 + threadIdx.x;
    if (i >= n4) return;
    float4 f = ((const float4*)in)[i];
    __half2 h0 = __floats2half2_rn(f.x, f.y);
    __half2 h1 = __floats2half2_rn(f.z, f.w);
    float2 a = __half22float2(h0), b = __half22float2(h1);
    __half2 l0 = __floats2half2_rn(f.x - a.x, f.y - a.y);
    __half2 l1 = __floats2half2_rn(f.z - b.x, f.w - b.y);
    ((__half2*)hi)[2*i]   = h0; ((__half2*)hi)[2*i+1] = h1;
    ((__half2*)lo)[2*i]   = l0; ((__half2*)lo)[2*i+1] = l1;
}

// all 4 weights in one launch: blockIdx.z selects the matrix
__global__ void __launch_bounds__(256)
split_wT4(const float* __restrict__ W0, const float* __restrict__ W1,
          const float* __restrict__ W2, const float* __restrict__ W3,
          __half* __restrict__ hiT, __half* __restrict__ loT) {
    __shared__ float t[32][33];
    const int z = blockIdx.z;
    const float* W = z == 0 ? W0 : (z == 1 ? W1 : (z == 2 ? W2 : W3));
    __half* hT = hiT + (size_t)z * EE * EE;
    __half* lT = loT + (size_t)z * EE * EE;
    const int r0 = blockIdx.y * 32, c0 = blockIdx.x * 32;
    const int tx = threadIdx.x & 31, ty = threadIdx.x >> 5;   // 32 x 8
#pragma unroll
    for (int j = 0; j < 4; j++)
        t[ty + 8*j][tx] = W[(size_t)(r0 + ty + 8*j) * EE + c0 + tx];
    __syncthreads();
#pragma unroll
    for (int j = 0; j < 4; j++) {
        float f = t[tx][ty + 8*j];     // = W[r0+tx][c0+ty+8j]
        __half h = __float2half_rn(f);
        size_t o = (size_t)(c0 + ty + 8*j) * EE + r0 + tx;
        hT[o] = h;
        lT[o] = __float2half_rn(f - __half2float(h));
    }
}

// ---------------------------------------------------------------------------
// fp16x2 GEMM v4: tile 128x128, 8 warps, BK=32, 2-stage cp.async.
// STREAMS: 3 = compensated; 1 = hi*hi only.
// MODE: 0=float out+bias; 12=Q/K fused (blockIdx.z: 0->Q scale+store, 1->K);
//       3=V (fp16 hi, transposed [bh][d][s]).
// ---------------------------------------------------------------------------
#define G_SMEM 81920

template <int MODE, int STREAMS>
__global__ void __launch_bounds__(256)
gemm16(const __half* __restrict__ Ah, const __half* __restrict__ Al,
       const __half* __restrict__ Bh0, const __half* __restrict__ Bl,
       const float* __restrict__ bias0, float* __restrict__ outf,
       __half* __restrict__ ohi0, __half* __restrict__ olo,
       const __half* __restrict__ Bh1, const float* __restrict__ bias1,
       __half* __restrict__ ohi1) {
    extern __shared__ __half sm[];

    const int tid  = threadIdx.x;
    const int lane = tid & 31;
    const int warp = tid >> 5;
    const int wm   = (warp >> 1) * 32;     // 0..96
    const int wn   = (warp & 1) * 64;      // 0 or 64
    const int m0   = blockIdx.x * 128;
    const int n0   = blockIdx.y * 128;
    const uint32_t smb = smem_u32(sm);

    const __half* Bh = Bh0;
    const float*  bias = bias0;
    __half* ohi = ohi0;
    if (MODE == 12 && blockIdx.z) { Bh = Bh1; bias = bias1; ohi = ohi1; }

    const int lrow = (lane & 7) + ((lane & 16) >> 1);
    const int lcol = (lane & 8);

    float acc[2][8][4];
#pragma unroll
    for (int mf = 0; mf < 2; mf++)
#pragma unroll
        for (int nf = 0; nf < 8; nf++)
#pragma unroll
            for (int i = 0; i < 4; i++) acc[mf][nf][i] = 0.f;

    auto load_stage = [&](int st, int k0) {
        if (STREAMS == 3) {
#pragma unroll
            for (int i = 0; i < 8; i++) {
                const int u = tid + i * 256;      // 0..2047
                const int t = u >> 9;              // 0=Ah 1=Al 2=Bh 3=Bl
                const int w = u & 511;
                const int row = w >> 2, c8 = (w & 3) * 8;
                const __half* src;
                if (t == 0)      src = Ah + (size_t)(m0 + row) * EE + k0 + c8;
                else if (t == 1) src = Al + (size_t)(m0 + row) * EE + k0 + c8;
                else if (t == 2) src = Bh + (size_t)(n0 + row) * EE + k0 + c8;
                else             src = Bl + (size_t)(n0 + row) * EE + k0 + c8;
                const uint32_t dsth = st * 20480 + t * 5120 + row * 40 + c8;
                cpa16(smb + dsth * 2, src);
            }
        } else {
#pragma unroll
            for (int i = 0; i < 4; i++) {
                const int u = tid + i * 256;      // 0..1023
                const int t = u >> 9;              // 0=Ah 1=Bh
                const int w = u & 511;
                const int row = w >> 2, c8 = (w & 3) * 8;
                const __half* src = t ? Bh + (size_t)(n0 + row) * EE + k0 + c8
                                      : Ah + (size_t)(m0 + row) * EE + k0 + c8;
                const uint32_t dsth = st * 20480 + t * 10240 + row * 40 + c8;
                cpa16(smb + dsth * 2, src);
            }
        }
        cpcommit();
    };

    load_stage(0, 0);
    const int NC = EE / 32;   // 24
    for (int c = 0; c < NC; c++) {
        const int st = c & 1;
        if (c + 1 < NC) { load_stage(st ^ 1, (c + 1) * 32); cpwait<1>(); }
        else            { cpwait<0>(); }
        __syncthreads();

        const uint32_t aH = smb + (st * 20480) * 2;
        const uint32_t aL = aH + 5120 * 2;
        const uint32_t bH = smb + (st * 20480 + 10240) * 2;
        const uint32_t bL = bH + 5120 * 2;

#pragma unroll
        for (int kk = 0; kk < 2; kk++) {
            const int cc = kk * 16;
            unsigned a_h[2][4], a_l[2][4];
#pragma unroll
            for (int mf = 0; mf < 2; mf++) {
                const int ar = wm + mf * 16 + (lane & 15);
                const int ac = cc + ((lane & 16) >> 1);
                ldsm4(a_h[mf][0], a_h[mf][1], a_h[mf][2], a_h[mf][3],
                      aH + (ar * 40 + ac) * 2);
                if (STREAMS == 3)
                    ldsm4(a_l[mf][0], a_l[mf][1], a_l[mf][2], a_l[mf][3],
                          aL + (ar * 40 + ac) * 2);
            }
#pragma unroll
            for (int p = 0; p < 4; p++) {
                const int br = wn + p * 16 + lrow;
                const int bc = cc + lcol;
                unsigned bh[4], bl[4];
                ldsm4(bh[0], bh[1], bh[2], bh[3], bH + (br * 40 + bc) * 2);
                if (STREAMS == 3)
                    ldsm4(bl[0], bl[1], bl[2], bl[3], bL + (br * 40 + bc) * 2);
#pragma unroll
                for (int q = 0; q < 2; q++) {
                    const int nf = 2 * p + q;
                    mma16(acc[0][nf], a_h[0], bh[2*q], bh[2*q+1]);
                    mma16(acc[1][nf], a_h[1], bh[2*q], bh[2*q+1]);
                    if (STREAMS == 3) {
                        mma16(acc[0][nf], a_h[0], bl[2*q], bl[2*q+1]);
                        mma16(acc[1][nf], a_h[1], bl[2*q], bl[2*q+1]);
                        mma16(acc[0][nf], a_l[0], bh[2*q], bh[2*q+1]);
                        mma16(acc[1][nf], a_l[1], bh[2*q], bh[2*q+1]);
                    }
                }
            }
        }
        __syncthreads();
    }

    // Epilogue: C layout r = g(+8), c = 2*t4(+1)
    const int g  = lane >> 2;
    const int t4 = lane & 3;
    const bool isQ = (MODE == 12) && (blockIdx.z == 0);
#pragma unroll
    for (int nf = 0; nf < 8; nf++) {
        const int nl = wn + nf * 8 + 2 * t4;       // 0..127 (even)
        const int n  = n0 + nl;
        const int hh_ = n >> 6;                    // head
        const int dl  = nl & 63;
        const float b0 = bias[n], b1 = bias[n + 1];
#pragma unroll
        for (int mf = 0; mf < 2; mf++) {
            const int m_lo = m0 + wm + mf * 16 + g;
            const int m_hi = m_lo + 8;
            float v0 = acc[mf][nf][0] + b0, v1 = acc[mf][nf][1] + b1;
            float v2 = acc[mf][nf][2] + b0, v3 = acc[mf][nf][3] + b1;
            if (MODE == 0) {
                *(float2*)(outf + (size_t)m_lo * EE + n) = make_float2(v0, v1);
                *(float2*)(outf + (size_t)m_hi * EE + n) = make_float2(v2, v3);
            } else if (MODE == 12) {
                if (isQ) {
                    const float qs = 0.125f * LOG2E;
                    v0 *= qs; v1 *= qs; v2 *= qs; v3 *= qs;
                }
                const int b_lo = m_lo >> 11, s_lo = m_lo & (SS - 1);
                const int b_hi = m_hi >> 11, s_hi = m_hi & (SS - 1);
                size_t o_lo = (((size_t)(b_lo * HH + hh_)) * SS + s_lo) * DD + dl;
                size_t o_hi = (((size_t)(b_hi * HH + hh_)) * SS + s_hi) * DD + dl;
                *(unsigned*)(ohi + o_lo) = h2u(__floats2half2_rn(v0, v1));
                *(unsigned*)(ohi + o_hi) = h2u(__floats2half2_rn(v2, v3));
            } else {  // MODE 3: V (hi only) transposed [bh][d][s]
                const int b_lo = m_lo >> 11, s_lo = m_lo & (SS - 1);
                const int b_hi = m_hi >> 11, s_hi = m_hi & (SS - 1);
                const size_t base_lo = ((size_t)(b_lo * HH + hh_)) * DD * SS;
                const size_t base_hi = ((size_t)(b_hi * HH + hh_)) * DD * SS;
                float vs[4] = {v0, v1, v2, v3};
#pragma unroll
                for (int e = 0; e < 4; e++) {
                    const int d = dl + (e & 1);
                    const size_t o = (e < 2 ? base_lo : base_hi) +
                                     (size_t)d * SS + (e < 2 ? s_lo : s_hi);
                    ohi[o] = __float2half_rn(vs[e]);
                }
            }
        }
    }
}

// ---------------------------------------------------------------------------
// Flash attention v5 (R10 config — the proven 384.5us shape):
// qtile 64, 4 warps / 128 thr, ktile 64 double-buffered cp.async.
// Q/K/V fp16 hi-only, log2-domain, fp16x2 exp, ones-MMA rowsum,
// ALiBi window slope2*k <= 40.
// ---------------------------------------------------------------------------
__global__ void __launch_bounds__(128)
attn16(const __half* __restrict__ Qh, const __half* __restrict__ Kh,
       const __half* __restrict__ Vth,
       __half* __restrict__ Ohi, __half* __restrict__ Olo) {
    __shared__ __half kv[2][2][64*72];

    const int tid  = threadIdx.x;
    const int lane = tid & 31;
    const int warp = tid >> 5;
    const int g    = lane >> 2;
    const int t4   = lane & 3;
    const uint32_t smb = smem_u32(kv);

    const int lrow = (lane & 7) + ((lane & 16) >> 1);
    const int lcol = (lane & 8);

    const int bh = blockIdx.y;
    const int h  = bh % HH;
    const int q0 = blockIdx.x * 64;
    const float slope2 = c_slopes[h] * LOG2E;

    const __half* Qhb = Qh + (size_t)bh * SS * DD;
    const __half* Khb = Kh + (size_t)bh * SS * DD;
    const __half* Vhb = Vth + (size_t)bh * DD * SS;

    const int r0 = q0 + warp * 16 + g;

    unsigned qh[4][4];
#pragma unroll
    for (int kk = 0; kk < 4; kk++) {
        const int c = kk * 16 + 2 * t4;
        qh[kk][0] = *(const unsigned*)(Qhb + (size_t)r0 * DD + c);
        qh[kk][1] = *(const unsigned*)(Qhb + (size_t)(r0 + 8) * DD + c);
        qh[kk][2] = *(const unsigned*)(Qhb + (size_t)r0 * DD + c + 8);
        qh[kk][3] = *(const unsigned*)(Qhb + (size_t)(r0 + 8) * DD + c + 8);
    }

    float Oacc[8][4];
#pragma unroll
    for (int i = 0; i < 8; i++)
#pragma unroll
        for (int j = 0; j < 4; j++) Oacc[i][j] = 0.f;
    float mrow0 = -1e30f, mrow1 = -1e30f, lrow0f = 0.f, lrow1f = 0.f;

    const int ktLast = q0 >> 6;
    int ktEnd = ktLast;
    {
        const int ctile = ((int)(40.f / slope2)) >> 6;
        if (ctile < ktEnd) ktEnd = ctile;
    }

    auto load_kv = [&](int st, int k0) {
#pragma unroll
        for (int i = 0; i < 8; i++) {
            const int u = tid + i * 128;       // 0..1023
            const int t = u >> 9;              // 0=K, 1=Vt
            const int w = u & 511;
            const int r = w >> 3, c8 = (w & 7) * 8;
            const __half* src = t ? (Vhb + (size_t)r * SS + k0 + c8)
                                  : (Khb + (size_t)(k0 + r) * DD + c8);
            const uint32_t dst = smb + (((st * 2 + t) * 4608) + r * 72 + c8) * 2;
            cpa16(dst, src);
        }
        cpcommit();
    };

    load_kv(0, 0);
    for (int kt = 0; kt <= ktEnd; kt++) {
        const int k0 = kt * 64;
        const int st = kt & 1;
        if (kt < ktEnd) { load_kv(st ^ 1, k0 + 64); cpwait<1>(); }
        else            { cpwait<0>(); }
        __syncthreads();

        const uint32_t ksh = smb + (st * 2) * 4608 * 2;
        const uint32_t vth = smb + (st * 2 + 1) * 4608 * 2;

        float S[8][4];
#pragma unroll
        for (int j = 0; j < 8; j++)
#pragma unroll
            for (int i = 0; i < 4; i++) S[j][i] = 0.f;
#pragma unroll
        for (int kk = 0; kk < 4; kk++) {
            const int cc = kk * 16 + lcol;
#pragma unroll
            for (int jp = 0; jp < 4; jp++) {
                const int br = jp * 16 + lrow;
                unsigned bh_[4];
                ldsm4(bh_[0], bh_[1], bh_[2], bh_[3], ksh + (br * 72 + cc) * 2);
                mma16(S[2*jp],     qh[kk], bh_[0], bh_[1]);
                mma16(S[2*jp + 1], qh[kk], bh_[2], bh_[3]);
            }
        }

        // ALiBi (-slope2*k; +slope2*q row term cancels in softmax) + causal
        const bool edge = (kt == ktLast);
        float tm0 = -1e30f, tm1 = -1e30f;
#pragma unroll
        for (int j = 0; j < 8; j++) {
            const int kc0 = k0 + j * 8 + 2 * t4;
            const float c0 = -slope2 * (float)kc0;
            const float c1 = c0 - slope2;
            S[j][0] += c0;
            S[j][1] += c1;
            S[j][2] += c0;
            S[j][3] += c1;
            if (edge) {
                if (kc0 > r0)         S[j][0] = -1e30f;
                if (kc0 + 1 > r0)     S[j][1] = -1e30f;
                if (kc0 > r0 + 8)     S[j][2] = -1e30f;
                if (kc0 + 1 > r0 + 8) S[j][3] = -1e30f;
            }
            tm0 = fmaxf(tm0, fmaxf(S[j][0], S[j][1]));
            tm1 = fmaxf(tm1, fmaxf(S[j][2], S[j][3]));
        }
        tm0 = fmaxf(tm0, __shfl_xor_sync(0xffffffffu, tm0, 1));
        tm0 = fmaxf(tm0, __shfl_xor_sync(0xffffffffu, tm0, 2));
        tm1 = fmaxf(tm1, __shfl_xor_sync(0xffffffffu, tm1, 1));
        tm1 = fmaxf(tm1, __shfl_xor_sync(0xffffffffu, tm1, 2));

        const float mn0 = fmaxf(mrow0, tm0);
        const float mn1 = fmaxf(mrow1, tm1);
        const float al0 = ex2(mrow0 - mn0);
        const float al1 = ex2(mrow1 - mn1);
        mrow0 = mn0; mrow1 = mn1;
#pragma unroll
        for (int i = 0; i < 8; i++) {
            Oacc[i][0] *= al0; Oacc[i][1] *= al0;
            Oacc[i][2] *= al1; Oacc[i][3] *= al1;
        }

        // P = 2^(S - m) fp16 pairs (A-frag layout); rowsum via ones-MMA.
        float Lacc[4] = {0.f, 0.f, 0.f, 0.f};
#pragma unroll
        for (int jj = 0; jj < 4; jj++) {
            unsigned ph[4];
            ph[0] = h2u(h2exp2(__floats2half2_rn(S[2*jj][0] - mn0, S[2*jj][1] - mn0)));
            ph[1] = h2u(h2exp2(__floats2half2_rn(S[2*jj][2] - mn1, S[2*jj][3] - mn1)));
            ph[2] = h2u(h2exp2(__floats2half2_rn(S[2*jj+1][0] - mn0, S[2*jj+1][1] - mn0)));
            ph[3] = h2u(h2exp2(__floats2half2_rn(S[2*jj+1][2] - mn1, S[2*jj+1][3] - mn1)));
            mma16(Lacc, ph, 0x3C003C00u, 0x3C003C00u);   // rowsum
            const int cc = jj * 16 + lcol;
#pragma unroll
            for (int dp = 0; dp < 4; dp++) {
                const int d0 = 2 * dp, d1 = d0 + 1;
                const int vr = dp * 16 + lrow;
                unsigned vh[4];
                ldsm4(vh[0], vh[1], vh[2], vh[3], vth + (vr * 72 + cc) * 2);
                mma16(Oacc[d0], ph, vh[0], vh[1]);
                mma16(Oacc[d1], ph, vh[2], vh[3]);
            }
        }
        lrow0f = lrow0f * al0 + Lacc[0];
        lrow1f = lrow1f * al1 + Lacc[2];
        __syncthreads();
    }

    const float inv0 = 1.f / lrow0f;
    const float inv1 = 1.f / lrow1f;
    __half* OhB = Ohi + (size_t)bh * SS * DD;
    __half* OlB = Olo + (size_t)bh * SS * DD;
#pragma unroll
    for (int dn = 0; dn < 8; dn++) {
        const int col = dn * 8 + 2 * t4;
        unsigned hh, ll;
        fsplit2(Oacc[dn][0] * inv0, Oacc[dn][1] * inv0, hh, ll);
        *(unsigned*)(OhB + (size_t)r0 * DD + col) = hh;
        *(unsigned*)(OlB + (size_t)r0 * DD + col) = ll;
        fsplit2(Oacc[dn][2] * inv1, Oacc[dn][3] * inv1, hh, ll);
        *(unsigned*)(OhB + (size_t)(r0 + 8) * DD + col) = hh;
        *(unsigned*)(OlB + (size_t)(r0 + 8) * DD + col) = ll;
    }
}

// ---------------------------------------------------------------------------
extern "C" void kernel_launch(void* const* d_in, const int* in_sizes, int n_in,
                              void* d_out, int out_size) {
    const float* x  = (const float*)d_in[0];
    const float* Wq = (const float*)d_in[1];
    const float* bq = (const float*)d_in[2];
    const float* Wk = (const float*)d_in[3];
    const float* bk = (const float*)d_in[4];
    const float* Wv = (const float*)d_in[5];
    const float* bv = (const float*)d_in[6];
    const float* Wo = (const float*)d_in[7];
    const float* bo = (const float*)d_in[8];
    float* out = (float*)d_out;

    __half *xhi, *xlo, *wThi, *wTlo, *qhi, *khi, *vthi, *ohi, *olo;
    cudaGetSymbolAddress((void**)&xhi, g_xhi);
    cudaGetSymbolAddress((void**)&xlo, g_xlo);
    cudaGetSymbolAddress((void**)&wThi, g_wThi);
    cudaGetSymbolAddress((void**)&wTlo, g_wTlo);
    cudaGetSymbolAddress((void**)&qhi, g_qhi);
    cudaGetSymbolAddress((void**)&khi, g_khi);
    cudaGetSymbolAddress((void**)&vthi, g_vthi);
    cudaGetSymbolAddress((void**)&ohi, g_ohi);
    cudaGetSymbolAddress((void**)&olo, g_olo);

    cudaFuncSetAttribute(gemm16<0,3>,  cudaFuncAttributeMaxDynamicSharedMemorySize, G_SMEM);
    cudaFuncSetAttribute(gemm16<12,1>, cudaFuncAttributeMaxDynamicSharedMemorySize, G_SMEM);
    cudaFuncSetAttribute(gemm16<3,3>,  cudaFuncAttributeMaxDynamicSharedMemorySize, G_SMEM);

    // prepass
    const int n4 = MM * EE / 4;
    split_vec<<<(n4 + 255) / 256, 256>>>(x, xhi, xlo, n4);
    dim3 wt4(24, 24, 4);
    split_wT4<<<wt4, 256>>>(Wq, Wk, Wv, Wo, wThi, wTlo);

    // Q + K fused (STREAMS=1): grid.z selects weight/bias/output
    dim3 gqk(MM / 128, EE / 128, 2);   // 64 x 6 x 2
    gemm16<12,1><<<gqk, 256, G_SMEM>>>(xhi, nullptr, wThi + 0 * EE * EE, nullptr,
                                       bq, nullptr, qhi, nullptr,
                                       wThi + 1 * EE * EE, bk, khi);
    // V (STREAMS=3)
    dim3 gg(MM / 128, EE / 128);       // 64 x 6
    gemm16<3,3><<<gg, 256, G_SMEM>>>(xhi, xlo, wThi + 2 * EE * EE, wTlo + 2 * EE * EE,
                                     bv, nullptr, vthi, nullptr,
                                     nullptr, nullptr, nullptr);

    dim3 ga(SS / 64, BB * HH);         // 32 x 48
    attn16<<<ga, 128>>>(qhi, khi, vthi, ohi, olo);

    // [B,H,S,D] flat == [B*S, E] (reference's head-major flatten)
    gemm16<0,3><<<gg, 256, G_SMEM>>>(ohi, olo, wThi + 3 * EE * EE, wTlo + 3 * EE * EE,
                                     bo, out, nullptr, nullptr,
                                     nullptr, nullptr, nullptr);
}

// round 13
// speedup vs baseline: 1.3257x; 1.2320x over previous
#include <cuda_runtime.h>
#include <cuda_fp16.h>
#include <cstdint>
#include <cstddef>

#define BB 4
#define HH 12
#define SS 2048
#define DD 64
#define EE 768
#define MM (BB*SS)
#define NT (BB*HH*SS*DD)   // 6291456

// ---------------- scratch (__device__ globals; no allocation) --------------
__device__ __half g_xhi[MM*EE];
__device__ __half g_wThi[4*EE*EE], g_wTlo[EE*EE];   // lo only for Wo
__device__ __half g_qhi[NT];
__device__ __half g_khi[NT];
__device__ __half g_vthi[NT];              // V transposed: [bh][d][s] (hi only)
__device__ __half g_ohi[NT], g_olo[NT];
__device__ float  g_bqkv[3*EE];

#define LOG2E 1.4426950408889634f

__constant__ float c_slopes[HH] = {
    0.6299605249f, 0.396850263f, 0.25f, 0.1574901312f,
    0.0992125657f, 0.0625f, 0.0393725328f, 0.0248031414f,
    0.015625f, 0.0098431332f, 0.0062007854f, 0.00390625f};

// ---------------------------------------------------------------------------
__device__ __forceinline__ uint32_t smem_u32(const void* p) {
    uint32_t a;
    asm("{ .reg .u64 t; cvta.to.shared.u64 t, %1; cvt.u32.u64 %0, t; }"
        : "=r"(a) : "l"(p));
    return a;
}
__device__ __forceinline__ unsigned h2u(__half2 h) {
    return reinterpret_cast<unsigned&>(h);
}
__device__ __forceinline__ void fsplit2(float a, float b, unsigned& hi, unsigned& lo) {
    __half2 h = __floats2half2_rn(a, b);
    float2 hf = __half22float2(h);
    __half2 l = __floats2half2_rn(a - hf.x, b - hf.y);
    hi = h2u(h); lo = h2u(l);
}
__device__ __forceinline__ float ex2(float x) {
    float y;
    asm("ex2.approx.f32 %0, %1;" : "=f"(y) : "f"(x));
    return y;
}
__device__ __forceinline__ void mma16(float* d, const unsigned* a,
                                      unsigned b0, unsigned b1) {
    asm volatile(
        "mma.sync.aligned.m16n8k16.row.col.f32.f16.f16.f32 "
        "{%0,%1,%2,%3}, {%4,%5,%6,%7}, {%8,%9}, {%0,%1,%2,%3};"
        : "+f"(d[0]), "+f"(d[1]), "+f"(d[2]), "+f"(d[3])
        : "r"(a[0]), "r"(a[1]), "r"(a[2]), "r"(a[3]), "r"(b0), "r"(b1));
}
__device__ __forceinline__ void ldsm4(unsigned& r0, unsigned& r1,
                                      unsigned& r2, unsigned& r3, uint32_t a) {
    asm volatile("ldmatrix.sync.aligned.m8n8.x4.shared.b16 {%0,%1,%2,%3}, [%4];"
                 : "=r"(r0), "=r"(r1), "=r"(r2), "=r"(r3) : "r"(a));
}
__device__ __forceinline__ void cpa16(uint32_t dst, const void* src) {
    asm volatile("cp.async.cg.shared.global [%0], [%1], 16;"
                 :: "r"(dst), "l"(src));
}
__device__ __forceinline__ void cpcommit() {
    asm volatile("cp.async.commit_group;" ::: "memory");
}
template <int N>
__device__ __forceinline__ void cpwait() {
    asm volatile("cp.async.wait_group %0;" :: "n"(N) : "memory");
}

// ---------------------------------------------------------------------------
// prepass
// ---------------------------------------------------------------------------
__global__ void __launch_bounds__(256)
split_hi(const float* __restrict__ in, __half* __restrict__ hi, int n4) {
    int i = blockIdx.x * 256 + threadIdx.x;
    if (i >= n4) return;
    float4 f = ((const float4*)in)[i];
    ((__half2*)hi)[2*i]   = __floats2half2_rn(f.x, f.y);
    ((__half2*)hi)[2*i+1] = __floats2half2_rn(f.z, f.w);
}

__global__ void __launch_bounds__(256)
split_wT4(const float* __restrict__ W0, const float* __restrict__ W1,
          const float* __restrict__ W2, const float* __restrict__ W3,
          __half* __restrict__ hiT, __half* __restrict__ loT) {
    __shared__ float t[32][33];
    const int z = blockIdx.z;
    const float* W = z == 0 ? W0 : (z == 1 ? W1 : (z == 2 ? W2 : W3));
    __half* hT = hiT + (size_t)z * EE * EE;
    const int r0 = blockIdx.y * 32, c0 = blockIdx.x * 32;
    const int tx = threadIdx.x & 31, ty = threadIdx.x >> 5;   // 32 x 8
#pragma unroll
    for (int j = 0; j < 4; j++)
        t[ty + 8*j][tx] = W[(size_t)(r0 + ty + 8*j) * EE + c0 + tx];
    __syncthreads();
#pragma unroll
    for (int j = 0; j < 4; j++) {
        float f = t[tx][ty + 8*j];
        __half h = __float2half_rn(f);
        size_t o = (size_t)(c0 + ty + 8*j) * EE + r0 + tx;
        hT[o] = h;
        if (z == 3) loT[o] = __float2half_rn(f - __half2float(h));
    }
}

__global__ void __launch_bounds__(256)
pack_bias(const float* __restrict__ bq, const float* __restrict__ bk,
          const float* __restrict__ bv, float* __restrict__ dst) {
    int i = blockIdx.x * 256 + threadIdx.x;
    if (i < EE)            dst[i] = bq[i];
    else if (i < 2 * EE)   dst[i] = bk[i - EE];
    else if (i < 3 * EE)   dst[i] = bv[i - 2 * EE];
}

// ---------------------------------------------------------------------------
// fp16x2 GEMM: tile 128x128, 8 warps, BK=32, 2-stage cp.async.
// STREAMS: 3 = Ah*Bh+Ah*Bl+Al*Bh; 1 = Ah*Bh only.
// MODE 0: float out + bias.
// MODE 4: QKV fused; blockIdx.z: 0=Q (scale, ->oq), 1=K (->ok),
//         2=V (->ov transposed [bh][d][s]). All fp16 hi out.
// ---------------------------------------------------------------------------
#define G_SMEM 81920

template <int MODE, int STREAMS>
__global__ void __launch_bounds__(256)
gemm16(const __half* __restrict__ Ah, const __half* __restrict__ Al,
       const __half* __restrict__ BhBase, const __half* __restrict__ Bl,
       const float* __restrict__ biasBase, float* __restrict__ outf,
       __half* __restrict__ oq, __half* __restrict__ olo,
       __half* __restrict__ ok, __half* __restrict__ ov) {
    extern __shared__ __half sm[];

    const int tid  = threadIdx.x;
    const int lane = tid & 31;
    const int warp = tid >> 5;
    const int wm   = (warp >> 1) * 32;
    const int wn   = (warp & 1) * 64;
    const int m0   = blockIdx.x * 128;
    const int n0   = blockIdx.y * 128;
    const int z    = (MODE == 4) ? blockIdx.z : 0;
    const uint32_t smb = smem_u32(sm);

    const __half* Bh = (MODE == 4) ? BhBase + (size_t)z * EE * EE : BhBase;
    const float*  bias = (MODE == 4) ? biasBase + z * EE : biasBase;

    const int lrow = (lane & 7) + ((lane & 16) >> 1);
    const int lcol = (lane & 8);

    float acc[2][8][4];
#pragma unroll
    for (int mf = 0; mf < 2; mf++)
#pragma unroll
        for (int nf = 0; nf < 8; nf++)
#pragma unroll
            for (int i = 0; i < 4; i++) acc[mf][nf][i] = 0.f;

    auto load_stage = [&](int st, int k0) {
        if (STREAMS == 3) {
#pragma unroll
            for (int i = 0; i < 8; i++) {
                const int u = tid + i * 256;
                const int t = u >> 9;
                const int w = u & 511;
                const int row = w >> 2, c8 = (w & 3) * 8;
                const __half* src;
                if (t == 0)      src = Ah + (size_t)(m0 + row) * EE + k0 + c8;
                else if (t == 1) src = Al + (size_t)(m0 + row) * EE + k0 + c8;
                else if (t == 2) src = Bh + (size_t)(n0 + row) * EE + k0 + c8;
                else             src = Bl + (size_t)(n0 + row) * EE + k0 + c8;
                const uint32_t dsth = st * 20480 + t * 5120 + row * 40 + c8;
                cpa16(smb + dsth * 2, src);
            }
        } else {
#pragma unroll
            for (int i = 0; i < 4; i++) {
                const int u = tid + i * 256;
                const int t = u >> 9;
                const int w = u & 511;
                const int row = w >> 2, c8 = (w & 3) * 8;
                const __half* src = t ? Bh + (size_t)(n0 + row) * EE + k0 + c8
                                      : Ah + (size_t)(m0 + row) * EE + k0 + c8;
                const uint32_t dsth = st * 20480 + t * 10240 + row * 40 + c8;
                cpa16(smb + dsth * 2, src);
            }
        }
        cpcommit();
    };

    load_stage(0, 0);
    const int NC = EE / 32;
    for (int c = 0; c < NC; c++) {
        const int st = c & 1;
        if (c + 1 < NC) { load_stage(st ^ 1, (c + 1) * 32); cpwait<1>(); }
        else            { cpwait<0>(); }
        __syncthreads();

        const uint32_t aH = smb + (st * 20480) * 2;
        const uint32_t aL = aH + 5120 * 2;
        const uint32_t bH = smb + (st * 20480 + 10240) * 2;
        const uint32_t bL = bH + 5120 * 2;

#pragma unroll
        for (int kk = 0; kk < 2; kk++) {
            const int cc = kk * 16;
            unsigned a_h[2][4], a_l[2][4];
#pragma unroll
            for (int mf = 0; mf < 2; mf++) {
                const int ar = wm + mf * 16 + (lane & 15);
                const int ac = cc + ((lane & 16) >> 1);
                ldsm4(a_h[mf][0], a_h[mf][1], a_h[mf][2], a_h[mf][3],
                      aH + (ar * 40 + ac) * 2);
                if (STREAMS == 3)
                    ldsm4(a_l[mf][0], a_l[mf][1], a_l[mf][2], a_l[mf][3],
                          aL + (ar * 40 + ac) * 2);
            }
#pragma unroll
            for (int p = 0; p < 4; p++) {
                const int br = wn + p * 16 + lrow;
                const int bc = cc + lcol;
                unsigned bh[4], bl[4];
                ldsm4(bh[0], bh[1], bh[2], bh[3], bH + (br * 40 + bc) * 2);
                if (STREAMS == 3)
                    ldsm4(bl[0], bl[1], bl[2], bl[3], bL + (br * 40 + bc) * 2);
#pragma unroll
                for (int q = 0; q < 2; q++) {
                    const int nf = 2 * p + q;
                    mma16(acc[0][nf], a_h[0], bh[2*q], bh[2*q+1]);
                    mma16(acc[1][nf], a_h[1], bh[2*q], bh[2*q+1]);
                    if (STREAMS == 3) {
                        mma16(acc[0][nf], a_h[0], bl[2*q], bl[2*q+1]);
                        mma16(acc[1][nf], a_h[1], bl[2*q], bl[2*q+1]);
                        mma16(acc[0][nf], a_l[0], bh[2*q], bh[2*q+1]);
                        mma16(acc[1][nf], a_l[1], bh[2*q], bh[2*q+1]);
                    }
                }
            }
        }
        __syncthreads();
    }

    const int g  = lane >> 2;
    const int t4 = lane & 3;
#pragma unroll
    for (int nf = 0; nf < 8; nf++) {
        const int nl = wn + nf * 8 + 2 * t4;
        const int n  = n0 + nl;
        const int hh_ = n >> 6;
        const int dl  = nl & 63;
        const float b0 = bias[n], b1 = bias[n + 1];
#pragma unroll
        for (int mf = 0; mf < 2; mf++) {
            const int m_lo = m0 + wm + mf * 16 + g;
            const int m_hi = m_lo + 8;
            float v0 = acc[mf][nf][0] + b0, v1 = acc[mf][nf][1] + b1;
            float v2 = acc[mf][nf][2] + b0, v3 = acc[mf][nf][3] + b1;
            if (MODE == 0) {
                *(float2*)(outf + (size_t)m_lo * EE + n) = make_float2(v0, v1);
                *(float2*)(outf + (size_t)m_hi * EE + n) = make_float2(v2, v3);
            } else {
                const int b_lo = m_lo >> 11, s_lo = m_lo & (SS - 1);
                const int b_hi = m_hi >> 11, s_hi = m_hi & (SS - 1);
                if (z == 2) {          // V -> [bh][d][s]
                    const size_t base_lo = ((size_t)(b_lo * HH + hh_)) * DD * SS;
                    const size_t base_hi = ((size_t)(b_hi * HH + hh_)) * DD * SS;
                    float vs[4] = {v0, v1, v2, v3};
#pragma unroll
                    for (int e = 0; e < 4; e++) {
                        const int d = dl + (e & 1);
                        const size_t o = (e < 2 ? base_lo : base_hi) +
                                         (size_t)d * SS + (e < 2 ? s_lo : s_hi);
                        ov[o] = __float2half_rn(vs[e]);
                    }
                } else {
                    __half* dst = (z == 0) ? oq : ok;
                    if (z == 0) {
                        const float qs = 0.125f * LOG2E;
                        v0 *= qs; v1 *= qs; v2 *= qs; v3 *= qs;
                    }
                    size_t o_lo = (((size_t)(b_lo * HH + hh_)) * SS + s_lo) * DD + dl;
                    size_t o_hi = (((size_t)(b_hi * HH + hh_)) * SS + s_hi) * DD + dl;
                    *(unsigned*)(dst + o_lo) = h2u(__floats2half2_rn(v0, v1));
                    *(unsigned*)(dst + o_hi) = h2u(__floats2half2_rn(v2, v3));
                }
            }
        }
    }
}

// ---------------------------------------------------------------------------
// Flash attention (proven R10 shape).
// ---------------------------------------------------------------------------
__global__ void __launch_bounds__(128)
attn16(const __half* __restrict__ Qh, const __half* __restrict__ Kh,
       const __half* __restrict__ Vth,
       __half* __restrict__ Ohi, __half* __restrict__ Olo) {
    __shared__ __half kv[2][2][64*72];

    const int tid  = threadIdx.x;
    const int lane = tid & 31;
    const int warp = tid >> 5;
    const int g    = lane >> 2;
    const int t4   = lane & 3;
    const uint32_t smb = smem_u32(kv);

    const int lrow = (lane & 7) + ((lane & 16) >> 1);
    const int lcol = (lane & 8);

    const int bh = blockIdx.y;
    const int h  = bh % HH;
    const int q0 = blockIdx.x * 64;
    const float slope2 = c_slopes[h] * LOG2E;

    const __half* Qhb = Qh + (size_t)bh * SS * DD;
    const __half* Khb = Kh + (size_t)bh * SS * DD;
    const __half* Vhb = Vth + (size_t)bh * DD * SS;

    const int r0 = q0 + warp * 16 + g;

    unsigned qh[4][4];
#pragma unroll
    for (int kk = 0; kk < 4; kk++) {
        const int c = kk * 16 + 2 * t4;
        qh[kk][0] = *(const unsigned*)(Qhb + (size_t)r0 * DD + c);
        qh[kk][1] = *(const unsigned*)(Qhb + (size_t)(r0 + 8) * DD + c);
        qh[kk][2] = *(const unsigned*)(Qhb + (size_t)r0 * DD + c + 8);
        qh[kk][3] = *(const unsigned*)(Qhb + (size_t)(r0 + 8) * DD + c + 8);
    }

    float Oacc[8][4];
#pragma unroll
    for (int i = 0; i < 8; i++)
#pragma unroll
        for (int j = 0; j < 4; j++) Oacc[i][j] = 0.f;
    float mrow0 = -1e30f, mrow1 = -1e30f, lrow0f = 0.f, lrow1f = 0.f;

    const int ktLast = q0 >> 6;
    int ktEnd = ktLast;
    {
        const int ctile = ((int)(40.f / slope2)) >> 6;
        if (ctile < ktEnd) ktEnd = ctile;
    }

    auto load_kv = [&](int st, int k0) {
#pragma unroll
        for (int i = 0; i < 8; i++) {
            const int u = tid + i * 128;
            const int t = u >> 9;
            const int w = u & 511;
            const int r = w >> 3, c8 = (w & 7) * 8;
            const __half* src = t ? (Vhb + (size_t)r * SS + k0 + c8)
                                  : (Khb + (size_t)(k0 + r) * DD + c8);
            const uint32_t dst = smb + (((st * 2 + t) * 4608) + r * 72 + c8) * 2;
            cpa16(dst, src);
        }
        cpcommit();
    };

    load_kv(0, 0);
    for (int kt = 0; kt <= ktEnd; kt++) {
        const int k0 = kt * 64;
        const int st = kt & 1;
        if (kt < ktEnd) { load_kv(st ^ 1, k0 + 64); cpwait<1>(); }
        else            { cpwait<0>(); }
        __syncthreads();

        const uint32_t ksh = smb + (st * 2) * 4608 * 2;
        const uint32_t vth = smb + (st * 2 + 1) * 4608 * 2;

        float S[8][4];
#pragma unroll
        for (int j = 0; j < 8; j++)
#pragma unroll
            for (int i = 0; i < 4; i++) S[j][i] = 0.f;
#pragma unroll
        for (int kk = 0; kk < 4; kk++) {
            const int cc = kk * 16 + lcol;
#pragma unroll
            for (int jp = 0; jp < 4; jp++) {
                const int br = jp * 16 + lrow;
                unsigned bh_[4];
                ldsm4(bh_[0], bh_[1], bh_[2], bh_[3], ksh + (br * 72 + cc) * 2);
                mma16(S[2*jp],     qh[kk], bh_[0], bh_[1]);
                mma16(S[2*jp + 1], qh[kk], bh_[2], bh_[3]);
            }
        }

        const bool edge = (kt == ktLast);
        float tm0 = -1e30f, tm1 = -1e30f;
#pragma unroll
        for (int j = 0; j < 8; j++) {
            const int kc0 = k0 + j * 8 + 2 * t4;
            const float c0 = -slope2 * (float)kc0;
            const float c1 = c0 - slope2;
            S[j][0] += c0;
            S[j][1] += c1;
            S[j][2] += c0;
            S[j][3] += c1;
            if (edge) {
                if (kc0 > r0)         S[j][0] = -1e30f;
                if (kc0 + 1 > r0)     S[j][1] = -1e30f;
                if (kc0 > r0 + 8)     S[j][2] = -1e30f;
                if (kc0 + 1 > r0 + 8) S[j][3] = -1e30f;
            }
            tm0 = fmaxf(tm0, fmaxf(S[j][0], S[j][1]));
            tm1 = fmaxf(tm1, fmaxf(S[j][2], S[j][3]));
        }
        tm0 = fmaxf(tm0, __shfl_xor_sync(0xffffffffu, tm0, 1));
        tm0 = fmaxf(tm0, __shfl_xor_sync(0xffffffffu, tm0, 2));
        tm1 = fmaxf(tm1, __shfl_xor_sync(0xffffffffu, tm1, 1));
        tm1 = fmaxf(tm1, __shfl_xor_sync(0xffffffffu, tm1, 2));

        const float mn0 = fmaxf(mrow0, tm0);
        const float mn1 = fmaxf(mrow1, tm1);
        const float al0 = ex2(mrow0 - mn0);
        const float al1 = ex2(mrow1 - mn1);
        mrow0 = mn0; mrow1 = mn1;
#pragma unroll
        for (int i = 0; i < 8; i++) {
            Oacc[i][0] *= al0; Oacc[i][1] *= al0;
            Oacc[i][2] *= al1; Oacc[i][3] *= al1;
        }

        float Lacc[4] = {0.f, 0.f, 0.f, 0.f};
#pragma unroll
        for (int jj = 0; jj < 4; jj++) {
            unsigned ph[4];
            ph[0] = h2u(h2exp2(__floats2half2_rn(S[2*jj][0] - mn0, S[2*jj][1] - mn0)));
            ph[1] = h2u(h2exp2(__floats2half2_rn(S[2*jj][2] - mn1, S[2*jj][3] - mn1)));
            ph[2] = h2u(h2exp2(__floats2half2_rn(S[2*jj+1][0] - mn0, S[2*jj+1][1] - mn0)));
            ph[3] = h2u(h2exp2(__floats2half2_rn(S[2*jj+1][2] - mn1, S[2*jj+1][3] - mn1)));
            mma16(Lacc, ph, 0x3C003C00u, 0x3C003C00u);
            const int cc = jj * 16 + lcol;
#pragma unroll
            for (int dp = 0; dp < 4; dp++) {
                const int d0 = 2 * dp, d1 = d0 + 1;
                const int vr = dp * 16 + lrow;
                unsigned vh[4];
                ldsm4(vh[0], vh[1], vh[2], vh[3], vth + (vr * 72 + cc) * 2);
                mma16(Oacc[d0], ph, vh[0], vh[1]);
                mma16(Oacc[d1], ph, vh[2], vh[3]);
            }
        }
        lrow0f = lrow0f * al0 + Lacc[0];
        lrow1f = lrow1f * al1 + Lacc[2];
        __syncthreads();
    }

    const float inv0 = 1.f / lrow0f;
    const float inv1 = 1.f / lrow1f;
    __half* OhB = Ohi + (size_t)bh * SS * DD;
    __half* OlB = Olo + (size_t)bh * SS * DD;
#pragma unroll
    for (int dn = 0; dn < 8; dn++) {
        const int col = dn * 8 + 2 * t4;
        unsigned hh, ll;
        fsplit2(Oacc[dn][0] * inv0, Oacc[dn][1] * inv0, hh, ll);
        *(unsigned*)(OhB + (size_t)r0 * DD + col) = hh;
        *(unsigned*)(OlB + (size_t)r0 * DD + col) = ll;
        fsplit2(Oacc[dn][2] * inv1, Oacc[dn][3] * inv1, hh, ll);
        *(unsigned*)(OhB + (size_t)(r0 + 8) * DD + col) = hh;
        *(unsigned*)(OlB + (size_t)(r0 + 8) * DD + col) = ll;
    }
}

// ---------------------------------------------------------------------------
extern "C" void kernel_launch(void* const* d_in, const int* in_sizes, int n_in,
                              void* d_out, int out_size) {
    const float* x  = (const float*)d_in[0];
    const float* Wq = (const float*)d_in[1];
    const float* bq = (const float*)d_in[2];
    const float* Wk = (const float*)d_in[3];
    const float* bk = (const float*)d_in[4];
    const float* Wv = (const float*)d_in[5];
    const float* bv = (const float*)d_in[6];
    const float* Wo = (const float*)d_in[7];
    const float* bo = (const float*)d_in[8];
    float* out = (float*)d_out;

    __half *xhi, *wThi, *wTlo, *qhi, *khi, *vthi, *ohi, *olo;
    float* bqkv;
    cudaGetSymbolAddress((void**)&xhi, g_xhi);
    cudaGetSymbolAddress((void**)&wThi, g_wThi);
    cudaGetSymbolAddress((void**)&wTlo, g_wTlo);
    cudaGetSymbolAddress((void**)&qhi, g_qhi);
    cudaGetSymbolAddress((void**)&khi, g_khi);
    cudaGetSymbolAddress((void**)&vthi, g_vthi);
    cudaGetSymbolAddress((void**)&ohi, g_ohi);
    cudaGetSymbolAddress((void**)&olo, g_olo);
    cudaGetSymbolAddress((void**)&bqkv, g_bqkv);

    cudaFuncSetAttribute(gemm16<0,3>, cudaFuncAttributeMaxDynamicSharedMemorySize, G_SMEM);
    cudaFuncSetAttribute(gemm16<4,1>, cudaFuncAttributeMaxDynamicSharedMemorySize, G_SMEM);

    // prepass
    const int n4 = MM * EE / 4;
    split_hi<<<(n4 + 255) / 256, 256>>>(x, xhi, n4);
    dim3 wt4(24, 24, 4);
    split_wT4<<<wt4, 256>>>(Wq, Wk, Wv, Wo, wThi, wTlo);
    pack_bias<<<(3 * EE + 255) / 256, 256>>>(bq, bk, bv, bqkv);

    // Q + K + V fused, hi-only (blockIdx.z selects weight/bias/output)
    dim3 gqkv(MM / 128, EE / 128, 3);   // 64 x 6 x 3
    gemm16<4,1><<<gqkv, 256, G_SMEM>>>(xhi, nullptr, wThi, nullptr,
                                       bqkv, nullptr, qhi, nullptr, khi, vthi);

    dim3 ga(SS / 64, BB * HH);          // 32 x 48
    attn16<<<ga, 128>>>(qhi, khi, vthi, ohi, olo);

    // [B,H,S,D] flat == [B*S, E] (reference's head-major flatten)
    dim3 gg(MM / 128, EE / 128);        // 64 x 6
    gemm16<0,3><<<gg, 256, G_SMEM>>>(ohi, olo, wThi + 3 * EE * EE, wTlo,
                                     bo, out, nullptr, nullptr, nullptr, nullptr);
}

// round 14
// speedup vs baseline: 1.4318x; 1.0800x over previous
#include <cuda_runtime.h>
#include <cuda_fp16.h>
#include <cstdint>
#include <cstddef>

#define BB 4
#define HH 12
#define SS 2048
#define DD 64
#define EE 768
#define MM (BB*SS)
#define NT (BB*HH*SS*DD)   // 6291456

// ---------------- scratch (__device__ globals; no allocation) --------------
__device__ __half g_xhi[MM*EE];
__device__ __half g_wThi[4*EE*EE], g_wTlo[EE*EE];   // lo only for Wo
__device__ __half g_qhi[NT];
__device__ __half g_khi[NT];
__device__ __half g_vthi[NT];              // V transposed: [bh][d][s]
__device__ __half g_ohi[NT];
__device__ float  g_bqkv[3*EE];

#define LOG2E 1.4426950408889634f

__constant__ float c_slopes[HH] = {
    0.6299605249f, 0.396850263f, 0.25f, 0.1574901312f,
    0.0992125657f, 0.0625f, 0.0393725328f, 0.0248031414f,
    0.015625f, 0.0098431332f, 0.0062007854f, 0.00390625f};

// ---------------------------------------------------------------------------
__device__ __forceinline__ uint32_t smem_u32(const void* p) {
    uint32_t a;
    asm("{ .reg .u64 t; cvta.to.shared.u64 t, %1; cvt.u32.u64 %0, t; }"
        : "=r"(a) : "l"(p));
    return a;
}
__device__ __forceinline__ unsigned h2u(__half2 h) {
    return reinterpret_cast<unsigned&>(h);
}
__device__ __forceinline__ float ex2(float x) {
    float y;
    asm("ex2.approx.f32 %0, %1;" : "=f"(y) : "f"(x));
    return y;
}
__device__ __forceinline__ void mma16(float* d, const unsigned* a,
                                      unsigned b0, unsigned b1) {
    asm volatile(
        "mma.sync.aligned.m16n8k16.row.col.f32.f16.f16.f32 "
        "{%0,%1,%2,%3}, {%4,%5,%6,%7}, {%8,%9}, {%0,%1,%2,%3};"
        : "+f"(d[0]), "+f"(d[1]), "+f"(d[2]), "+f"(d[3])
        : "r"(a[0]), "r"(a[1]), "r"(a[2]), "r"(a[3]), "r"(b0), "r"(b1));
}
__device__ __forceinline__ void ldsm4(unsigned& r0, unsigned& r1,
                                      unsigned& r2, unsigned& r3, uint32_t a) {
    asm volatile("ldmatrix.sync.aligned.m8n8.x4.shared.b16 {%0,%1,%2,%3}, [%4];"
                 : "=r"(r0), "=r"(r1), "=r"(r2), "=r"(r3) : "r"(a));
}
__device__ __forceinline__ void cpa16(uint32_t dst, const void* src) {
    asm volatile("cp.async.cg.shared.global [%0], [%1], 16;"
                 :: "r"(dst), "l"(src));
}
__device__ __forceinline__ void cpcommit() {
    asm volatile("cp.async.commit_group;" ::: "memory");
}
template <int N>
__device__ __forceinline__ void cpwait() {
    asm volatile("cp.async.wait_group %0;" :: "n"(N) : "memory");
}

// ---------------------------------------------------------------------------
// prepass
// ---------------------------------------------------------------------------
__global__ void __launch_bounds__(256)
split_hi(const float* __restrict__ in, __half* __restrict__ hi, int n4) {
    int i = blockIdx.x * 256 + threadIdx.x;
    if (i >= n4) return;
    float4 f = ((const float4*)in)[i];
    ((__half2*)hi)[2*i]   = __floats2half2_rn(f.x, f.y);
    ((__half2*)hi)[2*i+1] = __floats2half2_rn(f.z, f.w);
}

__global__ void __launch_bounds__(256)
split_wT4(const float* __restrict__ W0, const float* __restrict__ W1,
          const float* __restrict__ W2, const float* __restrict__ W3,
          __half* __restrict__ hiT, __half* __restrict__ loT) {
    __shared__ float t[32][33];
    const int z = blockIdx.z;
    const float* W = z == 0 ? W0 : (z == 1 ? W1 : (z == 2 ? W2 : W3));
    __half* hT = hiT + (size_t)z * EE * EE;
    const int r0 = blockIdx.y * 32, c0 = blockIdx.x * 32;
    const int tx = threadIdx.x & 31, ty = threadIdx.x >> 5;   // 32 x 8
#pragma unroll
    for (int j = 0; j < 4; j++)
        t[ty + 8*j][tx] = W[(size_t)(r0 + ty + 8*j) * EE + c0 + tx];
    __syncthreads();
#pragma unroll
    for (int j = 0; j < 4; j++) {
        float f = t[tx][ty + 8*j];
        __half h = __float2half_rn(f);
        size_t o = (size_t)(c0 + ty + 8*j) * EE + r0 + tx;
        hT[o] = h;
        if (z == 3) loT[o] = __float2half_rn(f - __half2float(h));
    }
}

__global__ void __launch_bounds__(256)
pack_bias(const float* __restrict__ bq, const float* __restrict__ bk,
          const float* __restrict__ bv, float* __restrict__ dst) {
    int i = blockIdx.x * 256 + threadIdx.x;
    if (i < EE)            dst[i] = bq[i];
    else if (i < 2 * EE)   dst[i] = bk[i - EE];
    else if (i < 3 * EE)   dst[i] = bv[i - 2 * EE];
}

// ---------------------------------------------------------------------------
// fp16 GEMM v5: CTA tile 128x128, 16 warps (4x4, warp tile 32x32), 512 thr,
// BK=32, 2-stage cp.async. Smem/stage (halfs): A@0(5120), Bh@5120,
// Bl@10240 (STREAMS==2). Stage stride 5120*(1+STREAMS).
// STREAMS: 1 = Ah*Bh; 2 = Ah*Bh + Ah*Bl.
// MODE 0: float out + bias. MODE 4: QKV fused (z: 0=Q scale,1=K,2=V transp).
// ---------------------------------------------------------------------------
template <int MODE, int STREAMS>
__global__ void __launch_bounds__(512, 2)
gemm16(const __half* __restrict__ Ah,
       const __half* __restrict__ BhBase, const __half* __restrict__ Bl,
       const float* __restrict__ biasBase, float* __restrict__ outf,
       __half* __restrict__ oq, __half* __restrict__ ok,
       __half* __restrict__ ov) {
    extern __shared__ __half sm[];
    const int SSTRIDE = 5120 * (1 + STREAMS);

    const int tid  = threadIdx.x;
    const int lane = tid & 31;
    const int warp = tid >> 5;              // 0..15
    const int wm   = (warp >> 2) * 32;      // 0..96
    const int wn   = (warp & 3) * 32;       // 0..96
    const int m0   = blockIdx.x * 128;
    const int n0   = blockIdx.y * 128;
    const int z    = (MODE == 4) ? blockIdx.z : 0;
    const uint32_t smb = smem_u32(sm);

    const __half* Bh = (MODE == 4) ? BhBase + (size_t)z * EE * EE : BhBase;
    const float*  bias = (MODE == 4) ? biasBase + z * EE : biasBase;

    const int lrow = (lane & 7) + ((lane & 16) >> 1);
    const int lcol = (lane & 8);

    float acc[2][4][4];
#pragma unroll
    for (int mf = 0; mf < 2; mf++)
#pragma unroll
        for (int nf = 0; nf < 4; nf++)
#pragma unroll
            for (int i = 0; i < 4; i++) acc[mf][nf][i] = 0.f;

    auto load_stage = [&](int st, int k0) {
#pragma unroll
        for (int i = 0; i < (STREAMS + 1); i++) {
            const int u = tid + i * 512;       // A:0..511  Bh:512..1023  Bl:...
            const int t = u >> 9;
            const int w = u & 511;
            const int row = w >> 2, c8 = (w & 3) * 8;
            const __half* src;
            if (t == 0)      src = Ah + (size_t)(m0 + row) * EE + k0 + c8;
            else if (t == 1) src = Bh + (size_t)(n0 + row) * EE + k0 + c8;
            else             src = Bl + (size_t)(n0 + row) * EE + k0 + c8;
            const uint32_t dsth = st * SSTRIDE + t * 5120 + row * 40 + c8;
            cpa16(smb + dsth * 2, src);
        }
        cpcommit();
    };

    load_stage(0, 0);
    const int NC = EE / 32;   // 24
    for (int c = 0; c < NC; c++) {
        const int st = c & 1;
        if (c + 1 < NC) { load_stage(st ^ 1, (c + 1) * 32); cpwait<1>(); }
        else            { cpwait<0>(); }
        __syncthreads();

        const uint32_t aH = smb + (st * SSTRIDE) * 2;
        const uint32_t bH = smb + (st * SSTRIDE + 5120) * 2;
        const uint32_t bL = smb + (st * SSTRIDE + 10240) * 2;

#pragma unroll
        for (int kk = 0; kk < 2; kk++) {
            const int cc = kk * 16;
            unsigned a_h[2][4];
#pragma unroll
            for (int mf = 0; mf < 2; mf++) {
                const int ar = wm + mf * 16 + (lane & 15);
                const int ac = cc + ((lane & 16) >> 1);
                ldsm4(a_h[mf][0], a_h[mf][1], a_h[mf][2], a_h[mf][3],
                      aH + (ar * 40 + ac) * 2);
            }
#pragma unroll
            for (int p = 0; p < 2; p++) {
                const int br = wn + p * 16 + lrow;
                const int bc = cc + lcol;
                unsigned bh[4], bl[4];
                ldsm4(bh[0], bh[1], bh[2], bh[3], bH + (br * 40 + bc) * 2);
                if (STREAMS == 2)
                    ldsm4(bl[0], bl[1], bl[2], bl[3], bL + (br * 40 + bc) * 2);
#pragma unroll
                for (int q = 0; q < 2; q++) {
                    const int nf = 2 * p + q;
                    mma16(acc[0][nf], a_h[0], bh[2*q], bh[2*q+1]);
                    mma16(acc[1][nf], a_h[1], bh[2*q], bh[2*q+1]);
                    if (STREAMS == 2) {
                        mma16(acc[0][nf], a_h[0], bl[2*q], bl[2*q+1]);
                        mma16(acc[1][nf], a_h[1], bl[2*q], bl[2*q+1]);
                    }
                }
            }
        }
        __syncthreads();
    }

    const int g  = lane >> 2;
    const int t4 = lane & 3;
#pragma unroll
    for (int nf = 0; nf < 4; nf++) {
        const int nl = wn + nf * 8 + 2 * t4;
        const int n  = n0 + nl;
        const int hh_ = n >> 6;
        const int dl  = nl & 63;
        const float b0 = bias[n], b1 = bias[n + 1];
#pragma unroll
        for (int mf = 0; mf < 2; mf++) {
            const int m_lo = m0 + wm + mf * 16 + g;
            const int m_hi = m_lo + 8;
            float v0 = acc[mf][nf][0] + b0, v1 = acc[mf][nf][1] + b1;
            float v2 = acc[mf][nf][2] + b0, v3 = acc[mf][nf][3] + b1;
            if (MODE == 0) {
                *(float2*)(outf + (size_t)m_lo * EE + n) = make_float2(v0, v1);
                *(float2*)(outf + (size_t)m_hi * EE + n) = make_float2(v2, v3);
            } else {
                const int b_lo = m_lo >> 11, s_lo = m_lo & (SS - 1);
                const int b_hi = m_hi >> 11, s_hi = m_hi & (SS - 1);
                if (z == 2) {          // V -> [bh][d][s]
                    const size_t base_lo = ((size_t)(b_lo * HH + hh_)) * DD * SS;
                    const size_t base_hi = ((size_t)(b_hi * HH + hh_)) * DD * SS;
                    float vs[4] = {v0, v1, v2, v3};
#pragma unroll
                    for (int e = 0; e < 4; e++) {
                        const int d = dl + (e & 1);
                        const size_t o = (e < 2 ? base_lo : base_hi) +
                                         (size_t)d * SS + (e < 2 ? s_lo : s_hi);
                        ov[o] = __float2half_rn(vs[e]);
                    }
                } else {
                    __half* dst = (z == 0) ? oq : ok;
                    if (z == 0) {
                        const float qs = 0.125f * LOG2E;
                        v0 *= qs; v1 *= qs; v2 *= qs; v3 *= qs;
                    }
                    size_t o_lo = (((size_t)(b_lo * HH + hh_)) * SS + s_lo) * DD + dl;
                    size_t o_hi = (((size_t)(b_hi * HH + hh_)) * SS + s_hi) * DD + dl;
                    *(unsigned*)(dst + o_lo) = h2u(__floats2half2_rn(v0, v1));
                    *(unsigned*)(dst + o_hi) = h2u(__floats2half2_rn(v2, v3));
                }
            }
        }
    }
}

// ---------------------------------------------------------------------------
// Flash attention (proven R10 shape); O stored fp16 hi only.
// ---------------------------------------------------------------------------
__global__ void __launch_bounds__(128)
attn16(const __half* __restrict__ Qh, const __half* __restrict__ Kh,
       const __half* __restrict__ Vth, __half* __restrict__ Ohi) {
    __shared__ __half kv[2][2][64*72];

    const int tid  = threadIdx.x;
    const int lane = tid & 31;
    const int warp = tid >> 5;
    const int g    = lane >> 2;
    const int t4   = lane & 3;
    const uint32_t smb = smem_u32(kv);

    const int lrow = (lane & 7) + ((lane & 16) >> 1);
    const int lcol = (lane & 8);

    const int bh = blockIdx.y;
    const int h  = bh % HH;
    const int q0 = blockIdx.x * 64;
    const float slope2 = c_slopes[h] * LOG2E;

    const __half* Qhb = Qh + (size_t)bh * SS * DD;
    const __half* Khb = Kh + (size_t)bh * SS * DD;
    const __half* Vhb = Vth + (size_t)bh * DD * SS;

    const int r0 = q0 + warp * 16 + g;

    unsigned qh[4][4];
#pragma unroll
    for (int kk = 0; kk < 4; kk++) {
        const int c = kk * 16 + 2 * t4;
        qh[kk][0] = *(const unsigned*)(Qhb + (size_t)r0 * DD + c);
        qh[kk][1] = *(const unsigned*)(Qhb + (size_t)(r0 + 8) * DD + c);
        qh[kk][2] = *(const unsigned*)(Qhb + (size_t)r0 * DD + c + 8);
        qh[kk][3] = *(const unsigned*)(Qhb + (size_t)(r0 + 8) * DD + c + 8);
    }

    float Oacc[8][4];
#pragma unroll
    for (int i = 0; i < 8; i++)
#pragma unroll
        for (int j = 0; j < 4; j++) Oacc[i][j] = 0.f;
    float mrow0 = -1e30f, mrow1 = -1e30f, lrow0f = 0.f, lrow1f = 0.f;

    const int ktLast = q0 >> 6;
    int ktEnd = ktLast;
    {
        const int ctile = ((int)(40.f / slope2)) >> 6;
        if (ctile < ktEnd) ktEnd = ctile;
    }

    auto load_kv = [&](int st, int k0) {
#pragma unroll
        for (int i = 0; i < 8; i++) {
            const int u = tid + i * 128;
            const int t = u >> 9;
            const int w = u & 511;
            const int r = w >> 3, c8 = (w & 7) * 8;
            const __half* src = t ? (Vhb + (size_t)r * SS + k0 + c8)
                                  : (Khb + (size_t)(k0 + r) * DD + c8);
            const uint32_t dst = smb + (((st * 2 + t) * 4608) + r * 72 + c8) * 2;
            cpa16(dst, src);
        }
        cpcommit();
    };

    load_kv(0, 0);
    for (int kt = 0; kt <= ktEnd; kt++) {
        const int k0 = kt * 64;
        const int st = kt & 1;
        if (kt < ktEnd) { load_kv(st ^ 1, k0 + 64); cpwait<1>(); }
        else            { cpwait<0>(); }
        __syncthreads();

        const uint32_t ksh = smb + (st * 2) * 4608 * 2;
        const uint32_t vth = smb + (st * 2 + 1) * 4608 * 2;

        float S[8][4];
#pragma unroll
        for (int j = 0; j < 8; j++)
#pragma unroll
            for (int i = 0; i < 4; i++) S[j][i] = 0.f;
#pragma unroll
        for (int kk = 0; kk < 4; kk++) {
            const int cc = kk * 16 + lcol;
#pragma unroll
            for (int jp = 0; jp < 4; jp++) {
                const int br = jp * 16 + lrow;
                unsigned bh_[4];
                ldsm4(bh_[0], bh_[1], bh_[2], bh_[3], ksh + (br * 72 + cc) * 2);
                mma16(S[2*jp],     qh[kk], bh_[0], bh_[1]);
                mma16(S[2*jp + 1], qh[kk], bh_[2], bh_[3]);
            }
        }

        const bool edge = (kt == ktLast);
        float tm0 = -1e30f, tm1 = -1e30f;
#pragma unroll
        for (int j = 0; j < 8; j++) {
            const int kc0 = k0 + j * 8 + 2 * t4;
            const float c0 = -slope2 * (float)kc0;
            const float c1 = c0 - slope2;
            S[j][0] += c0;
            S[j][1] += c1;
            S[j][2] += c0;
            S[j][3] += c1;
            if (edge) {
                if (kc0 > r0)         S[j][0] = -1e30f;
                if (kc0 + 1 > r0)     S[j][1] = -1e30f;
                if (kc0 > r0 + 8)     S[j][2] = -1e30f;
                if (kc0 + 1 > r0 + 8) S[j][3] = -1e30f;
            }
            tm0 = fmaxf(tm0, fmaxf(S[j][0], S[j][1]));
            tm1 = fmaxf(tm1, fmaxf(S[j][2], S[j][3]));
        }
        tm0 = fmaxf(tm0, __shfl_xor_sync(0xffffffffu, tm0, 1));
        tm0 = fmaxf(tm0, __shfl_xor_sync(0xffffffffu, tm0, 2));
        tm1 = fmaxf(tm1, __shfl_xor_sync(0xffffffffu, tm1, 1));
        tm1 = fmaxf(tm1, __shfl_xor_sync(0xffffffffu, tm1, 2));

        const float mn0 = fmaxf(mrow0, tm0);
        const float mn1 = fmaxf(mrow1, tm1);
        const float al0 = ex2(mrow0 - mn0);
        const float al1 = ex2(mrow1 - mn1);
        mrow0 = mn0; mrow1 = mn1;
#pragma unroll
        for (int i = 0; i < 8; i++) {
            Oacc[i][0] *= al0; Oacc[i][1] *= al0;
            Oacc[i][2] *= al1; Oacc[i][3] *= al1;
        }

        float Lacc[4] = {0.f, 0.f, 0.f, 0.f};
#pragma unroll
        for (int jj = 0; jj < 4; jj++) {
            unsigned ph[4];
            ph[0] = h2u(h2exp2(__floats2half2_rn(S[2*jj][0] - mn0, S[2*jj][1] - mn0)));
            ph[1] = h2u(h2exp2(__floats2half2_rn(S[2*jj][2] - mn1, S[2*jj][3] - mn1)));
            ph[2] = h2u(h2exp2(__floats2half2_rn(S[2*jj+1][0] - mn0, S[2*jj+1][1] - mn0)));
            ph[3] = h2u(h2exp2(__floats2half2_rn(S[2*jj+1][2] - mn1, S[2*jj+1][3] - mn1)));
            mma16(Lacc, ph, 0x3C003C00u, 0x3C003C00u);
            const int cc = jj * 16 + lcol;
#pragma unroll
            for (int dp = 0; dp < 4; dp++) {
                const int d0 = 2 * dp, d1 = d0 + 1;
                const int vr = dp * 16 + lrow;
                unsigned vh[4];
                ldsm4(vh[0], vh[1], vh[2], vh[3], vth + (vr * 72 + cc) * 2);
                mma16(Oacc[d0], ph, vh[0], vh[1]);
                mma16(Oacc[d1], ph, vh[2], vh[3]);
            }
        }
        lrow0f = lrow0f * al0 + Lacc[0];
        lrow1f = lrow1f * al1 + Lacc[2];
        __syncthreads();
    }

    const float inv0 = 1.f / lrow0f;
    const float inv1 = 1.f / lrow1f;
    __half* OhB = Ohi + (size_t)bh * SS * DD;
#pragma unroll
    for (int dn = 0; dn < 8; dn++) {
        const int col = dn * 8 + 2 * t4;
        *(unsigned*)(OhB + (size_t)r0 * DD + col) =
            h2u(__floats2half2_rn(Oacc[dn][0] * inv0, Oacc[dn][1] * inv0));
        *(unsigned*)(OhB + (size_t)(r0 + 8) * DD + col) =
            h2u(__floats2half2_rn(Oacc[dn][2] * inv1, Oacc[dn][3] * inv1));
    }
}

// ---------------------------------------------------------------------------
extern "C" void kernel_launch(void* const* d_in, const int* in_sizes, int n_in,
                              void* d_out, int out_size) {
    const float* x  = (const float*)d_in[0];
    const float* Wq = (const float*)d_in[1];
    const float* bq = (const float*)d_in[2];
    const float* Wk = (const float*)d_in[3];
    const float* bk = (const float*)d_in[4];
    const float* Wv = (const float*)d_in[5];
    const float* bv = (const float*)d_in[6];
    const float* Wo = (const float*)d_in[7];
    const float* bo = (const float*)d_in[8];
    float* out = (float*)d_out;

    __half *xhi, *wThi, *wTlo, *qhi, *khi, *vthi, *ohi;
    float* bqkv;
    cudaGetSymbolAddress((void**)&xhi, g_xhi);
    cudaGetSymbolAddress((void**)&wThi, g_wThi);
    cudaGetSymbolAddress((void**)&wTlo, g_wTlo);
    cudaGetSymbolAddress((void**)&qhi, g_qhi);
    cudaGetSymbolAddress((void**)&khi, g_khi);
    cudaGetSymbolAddress((void**)&vthi, g_vthi);
    cudaGetSymbolAddress((void**)&ohi, g_ohi);
    cudaGetSymbolAddress((void**)&bqkv, g_bqkv);

    const int SM_QKV = 2 * 10240 * 2;   // 40960 B
    const int SM_O   = 2 * 15360 * 2;   // 61440 B
    cudaFuncSetAttribute(gemm16<4,1>, cudaFuncAttributeMaxDynamicSharedMemorySize, SM_QKV);
    cudaFuncSetAttribute(gemm16<0,2>, cudaFuncAttributeMaxDynamicSharedMemorySize, SM_O);

    // prepass
    const int n4 = MM * EE / 4;
    split_hi<<<(n4 + 255) / 256, 256>>>(x, xhi, n4);
    dim3 wt4(24, 24, 4);
    split_wT4<<<wt4, 256>>>(Wq, Wk, Wv, Wo, wThi, wTlo);
    pack_bias<<<(3 * EE + 255) / 256, 256>>>(bq, bk, bv, bqkv);

    // Q + K + V fused, hi-only
    dim3 gqkv(MM / 128, EE / 128, 3);   // 64 x 6 x 3
    gemm16<4,1><<<gqkv, 512, SM_QKV>>>(xhi, wThi, nullptr,
                                       bqkv, nullptr, qhi, khi, vthi);

    dim3 ga(SS / 64, BB * HH);          // 32 x 48
    attn16<<<ga, 128>>>(qhi, khi, vthi, ohi);

    // [B,H,S,D] flat == [B*S, E]; O = Ohi @ (Wo_hi + Wo_lo) + bo
    dim3 gg(MM / 128, EE / 128);        // 64 x 6
    gemm16<0,2><<<gg, 512, SM_O>>>(ohi, wThi + 3 * EE * EE, wTlo,
                                   bo, out, nullptr, nullptr, nullptr);
}

// round 15
// speedup vs baseline: 1.6200x; 1.1314x over previous
#include <cuda_runtime.h>
#include <cuda_fp16.h>
#include <cstdint>
#include <cstddef>

#define BB 4
#define HH 12
#define SS 2048
#define DD 64
#define EE 768
#define MM (BB*SS)
#define NT (BB*HH*SS*DD)   // 6291456

// ---------------- scratch (__device__ globals; no allocation) --------------
__device__ __half g_xhi[MM*EE];
__device__ __half g_wThi[4*EE*EE];
__device__ __half g_qhi[NT];
__device__ __half g_khi[NT];
__device__ __half g_vthi[NT];              // V transposed: [bh][d][s]
__device__ __half g_ohi[NT];
__device__ float  g_bqkv[3*EE];

#define LOG2E 1.4426950408889634f

__constant__ float c_slopes[HH] = {
    0.6299605249f, 0.396850263f, 0.25f, 0.1574901312f,
    0.0992125657f, 0.0625f, 0.0393725328f, 0.0248031414f,
    0.015625f, 0.0098431332f, 0.0062007854f, 0.00390625f};

// ---------------------------------------------------------------------------
__device__ __forceinline__ uint32_t smem_u32(const void* p) {
    uint32_t a;
    asm("{ .reg .u64 t; cvta.to.shared.u64 t, %1; cvt.u32.u64 %0, t; }"
        : "=r"(a) : "l"(p));
    return a;
}
__device__ __forceinline__ unsigned h2u(__half2 h) {
    return reinterpret_cast<unsigned&>(h);
}
__device__ __forceinline__ float ex2(float x) {
    float y;
    asm("ex2.approx.f32 %0, %1;" : "=f"(y) : "f"(x));
    return y;
}
__device__ __forceinline__ void mma16(float* d, const unsigned* a,
                                      unsigned b0, unsigned b1) {
    asm volatile(
        "mma.sync.aligned.m16n8k16.row.col.f32.f16.f16.f32 "
        "{%0,%1,%2,%3}, {%4,%5,%6,%7}, {%8,%9}, {%0,%1,%2,%3};"
        : "+f"(d[0]), "+f"(d[1]), "+f"(d[2]), "+f"(d[3])
        : "r"(a[0]), "r"(a[1]), "r"(a[2]), "r"(a[3]), "r"(b0), "r"(b1));
}
__device__ __forceinline__ void ldsm4(unsigned& r0, unsigned& r1,
                                      unsigned& r2, unsigned& r3, uint32_t a) {
    asm volatile("ldmatrix.sync.aligned.m8n8.x4.shared.b16 {%0,%1,%2,%3}, [%4];"
                 : "=r"(r0), "=r"(r1), "=r"(r2), "=r"(r3) : "r"(a));
}
__device__ __forceinline__ void cpa16(uint32_t dst, const void* src) {
    asm volatile("cp.async.cg.shared.global [%0], [%1], 16;"
                 :: "r"(dst), "l"(src));
}
__device__ __forceinline__ void cpcommit() {
    asm volatile("cp.async.commit_group;" ::: "memory");
}
template <int N>
__device__ __forceinline__ void cpwait() {
    asm volatile("cp.async.wait_group %0;" :: "n"(N) : "memory");
}

// ---------------------------------------------------------------------------
// prepass
// ---------------------------------------------------------------------------
__global__ void __launch_bounds__(256)
split_hi(const float* __restrict__ in, __half* __restrict__ hi, int n4) {
    int i = blockIdx.x * 256 + threadIdx.x;
    if (i >= n4) return;
    float4 f = ((const float4*)in)[i];
    ((__half2*)hi)[2*i]   = __floats2half2_rn(f.x, f.y);
    ((__half2*)hi)[2*i+1] = __floats2half2_rn(f.z, f.w);
}

__global__ void __launch_bounds__(256)
split_wT4(const float* __restrict__ W0, const float* __restrict__ W1,
          const float* __restrict__ W2, const float* __restrict__ W3,
          __half* __restrict__ hiT) {
    __shared__ float t[32][33];
    const int z = blockIdx.z;
    const float* W = z == 0 ? W0 : (z == 1 ? W1 : (z == 2 ? W2 : W3));
    __half* hT = hiT + (size_t)z * EE * EE;
    const int r0 = blockIdx.y * 32, c0 = blockIdx.x * 32;
    const int tx = threadIdx.x & 31, ty = threadIdx.x >> 5;   // 32 x 8
#pragma unroll
    for (int j = 0; j < 4; j++)
        t[ty + 8*j][tx] = W[(size_t)(r0 + ty + 8*j) * EE + c0 + tx];
    __syncthreads();
#pragma unroll
    for (int j = 0; j < 4; j++)
        hT[(size_t)(c0 + ty + 8*j) * EE + r0 + tx] = __float2half_rn(t[tx][ty + 8*j]);
}

__global__ void __launch_bounds__(256)
pack_bias(const float* __restrict__ bq, const float* __restrict__ bk,
          const float* __restrict__ bv, float* __restrict__ dst) {
    int i = blockIdx.x * 256 + threadIdx.x;
    if (i < EE)            dst[i] = bq[i];
    else if (i < 2 * EE)   dst[i] = bk[i - EE];
    else if (i < 3 * EE)   dst[i] = bv[i - 2 * EE];
}

// ---------------------------------------------------------------------------
// fp16 GEMM: CTA tile 128x128, 16 warps (4x4, warp tile 32x32), 512 thr,
// BK=32, 2-stage cp.async, hi*hi only (single stream).
// MODE 0: float out + bias. MODE 4: QKV fused (z: 0=Q scale,1=K,2=V transp).
// ---------------------------------------------------------------------------
#define SM_G 40960   // 2 stages x (A + B) x 5120 halfs x 2B

template <int MODE>
__global__ void __launch_bounds__(512, 2)
gemm16(const __half* __restrict__ Ah,
       const __half* __restrict__ BhBase,
       const float* __restrict__ biasBase, float* __restrict__ outf,
       __half* __restrict__ oq, __half* __restrict__ ok,
       __half* __restrict__ ov) {
    extern __shared__ __half sm[];
    const int SSTRIDE = 10240;

    const int tid  = threadIdx.x;
    const int lane = tid & 31;
    const int warp = tid >> 5;              // 0..15
    const int wm   = (warp >> 2) * 32;      // 0..96
    const int wn   = (warp & 3) * 32;       // 0..96
    const int m0   = blockIdx.x * 128;
    const int n0   = blockIdx.y * 128;
    const int z    = (MODE == 4) ? blockIdx.z : 0;
    const uint32_t smb = smem_u32(sm);

    const __half* Bh = (MODE == 4) ? BhBase + (size_t)z * EE * EE : BhBase;
    const float*  bias = (MODE == 4) ? biasBase + z * EE : biasBase;

    const int lrow = (lane & 7) + ((lane & 16) >> 1);
    const int lcol = (lane & 8);

    float acc[2][4][4];
#pragma unroll
    for (int mf = 0; mf < 2; mf++)
#pragma unroll
        for (int nf = 0; nf < 4; nf++)
#pragma unroll
            for (int i = 0; i < 4; i++) acc[mf][nf][i] = 0.f;

    auto load_stage = [&](int st, int k0) {
#pragma unroll
        for (int i = 0; i < 2; i++) {
            const int u = tid + i * 512;       // A:0..511  B:512..1023
            const int t = u >> 9;
            const int w = u & 511;
            const int row = w >> 2, c8 = (w & 3) * 8;
            const __half* src = t ? Bh + (size_t)(n0 + row) * EE + k0 + c8
                                  : Ah + (size_t)(m0 + row) * EE + k0 + c8;
            const uint32_t dsth = st * SSTRIDE + t * 5120 + row * 40 + c8;
            cpa16(smb + dsth * 2, src);
        }
        cpcommit();
    };

    load_stage(0, 0);
    const int NC = EE / 32;   // 24
    for (int c = 0; c < NC; c++) {
        const int st = c & 1;
        if (c + 1 < NC) { load_stage(st ^ 1, (c + 1) * 32); cpwait<1>(); }
        else            { cpwait<0>(); }
        __syncthreads();

        const uint32_t aH = smb + (st * SSTRIDE) * 2;
        const uint32_t bH = smb + (st * SSTRIDE + 5120) * 2;

#pragma unroll
        for (int kk = 0; kk < 2; kk++) {
            const int cc = kk * 16;
            unsigned a_h[2][4];
#pragma unroll
            for (int mf = 0; mf < 2; mf++) {
                const int ar = wm + mf * 16 + (lane & 15);
                const int ac = cc + ((lane & 16) >> 1);
                ldsm4(a_h[mf][0], a_h[mf][1], a_h[mf][2], a_h[mf][3],
                      aH + (ar * 40 + ac) * 2);
            }
#pragma unroll
            for (int p = 0; p < 2; p++) {
                const int br = wn + p * 16 + lrow;
                const int bc = cc + lcol;
                unsigned bh[4];
                ldsm4(bh[0], bh[1], bh[2], bh[3], bH + (br * 40 + bc) * 2);
#pragma unroll
                for (int q = 0; q < 2; q++) {
                    const int nf = 2 * p + q;
                    mma16(acc[0][nf], a_h[0], bh[2*q], bh[2*q+1]);
                    mma16(acc[1][nf], a_h[1], bh[2*q], bh[2*q+1]);
                }
            }
        }
        __syncthreads();
    }

    const int g  = lane >> 2;
    const int t4 = lane & 3;
#pragma unroll
    for (int nf = 0; nf < 4; nf++) {
        const int nl = wn + nf * 8 + 2 * t4;
        const int n  = n0 + nl;
        const int hh_ = n >> 6;
        const int dl  = nl & 63;
        const float b0 = bias[n], b1 = bias[n + 1];
#pragma unroll
        for (int mf = 0; mf < 2; mf++) {
            const int m_lo = m0 + wm + mf * 16 + g;
            const int m_hi = m_lo + 8;
            float v0 = acc[mf][nf][0] + b0, v1 = acc[mf][nf][1] + b1;
            float v2 = acc[mf][nf][2] + b0, v3 = acc[mf][nf][3] + b1;
            if (MODE == 0) {
                *(float2*)(outf + (size_t)m_lo * EE + n) = make_float2(v0, v1);
                *(float2*)(outf + (size_t)m_hi * EE + n) = make_float2(v2, v3);
            } else {
                const int b_lo = m_lo >> 11, s_lo = m_lo & (SS - 1);
                const int b_hi = m_hi >> 11, s_hi = m_hi & (SS - 1);
                if (z == 2) {          // V -> [bh][d][s]
                    const size_t base_lo = ((size_t)(b_lo * HH + hh_)) * DD * SS;
                    const size_t base_hi = ((size_t)(b_hi * HH + hh_)) * DD * SS;
                    float vs[4] = {v0, v1, v2, v3};
#pragma unroll
                    for (int e = 0; e < 4; e++) {
                        const int d = dl + (e & 1);
                        const size_t o = (e < 2 ? base_lo : base_hi) +
                                         (size_t)d * SS + (e < 2 ? s_lo : s_hi);
                        ov[o] = __float2half_rn(vs[e]);
                    }
                } else {
                    __half* dst = (z == 0) ? oq : ok;
                    if (z == 0) {
                        const float qs = 0.125f * LOG2E;
                        v0 *= qs; v1 *= qs; v2 *= qs; v3 *= qs;
                    }
                    size_t o_lo = (((size_t)(b_lo * HH + hh_)) * SS + s_lo) * DD + dl;
                    size_t o_hi = (((size_t)(b_hi * HH + hh_)) * SS + s_hi) * DD + dl;
                    *(unsigned*)(dst + o_lo) = h2u(__floats2half2_rn(v0, v1));
                    *(unsigned*)(dst + o_hi) = h2u(__floats2half2_rn(v2, v3));
                }
            }
        }
    }
}

// ---------------------------------------------------------------------------
// Flash attention (proven R10 shape); window 33 log2-units; O fp16 hi.
// ---------------------------------------------------------------------------
__global__ void __launch_bounds__(128)
attn16(const __half* __restrict__ Qh, const __half* __restrict__ Kh,
       const __half* __restrict__ Vth, __half* __restrict__ Ohi) {
    __shared__ __half kv[2][2][64*72];

    const int tid  = threadIdx.x;
    const int lane = tid & 31;
    const int warp = tid >> 5;
    const int g    = lane >> 2;
    const int t4   = lane & 3;
    const uint32_t smb = smem_u32(kv);

    const int lrow = (lane & 7) + ((lane & 16) >> 1);
    const int lcol = (lane & 8);

    const int bh = blockIdx.y;
    const int h  = bh % HH;
    const int q0 = blockIdx.x * 64;
    const float slope2 = c_slopes[h] * LOG2E;

    const __half* Qhb = Qh + (size_t)bh * SS * DD;
    const __half* Khb = Kh + (size_t)bh * SS * DD;
    const __half* Vhb = Vth + (size_t)bh * DD * SS;

    const int r0 = q0 + warp * 16 + g;

    unsigned qh[4][4];
#pragma unroll
    for (int kk = 0; kk < 4; kk++) {
        const int c = kk * 16 + 2 * t4;
        qh[kk][0] = *(const unsigned*)(Qhb + (size_t)r0 * DD + c);
        qh[kk][1] = *(const unsigned*)(Qhb + (size_t)(r0 + 8) * DD + c);
        qh[kk][2] = *(const unsigned*)(Qhb + (size_t)r0 * DD + c + 8);
        qh[kk][3] = *(const unsigned*)(Qhb + (size_t)(r0 + 8) * DD + c + 8);
    }

    float Oacc[8][4];
#pragma unroll
    for (int i = 0; i < 8; i++)
#pragma unroll
        for (int j = 0; j < 4; j++) Oacc[i][j] = 0.f;
    float mrow0 = -1e30f, mrow1 = -1e30f, lrow0f = 0.f, lrow1f = 0.f;

    const int ktLast = q0 >> 6;
    int ktEnd = ktLast;
    {
        const int ctile = ((int)(33.f / slope2)) >> 6;
        if (ctile < ktEnd) ktEnd = ctile;
    }

    auto load_kv = [&](int st, int k0) {
#pragma unroll
        for (int i = 0; i < 8; i++) {
            const int u = tid + i * 128;
            const int t = u >> 9;
            const int w = u & 511;
            const int r = w >> 3, c8 = (w & 7) * 8;
            const __half* src = t ? (Vhb + (size_t)r * SS + k0 + c8)
                                  : (Khb + (size_t)(k0 + r) * DD + c8);
            const uint32_t dst = smb + (((st * 2 + t) * 4608) + r * 72 + c8) * 2;
            cpa16(dst, src);
        }
        cpcommit();
    };

    load_kv(0, 0);
    for (int kt = 0; kt <= ktEnd; kt++) {
        const int k0 = kt * 64;
        const int st = kt & 1;
        if (kt < ktEnd) { load_kv(st ^ 1, k0 + 64); cpwait<1>(); }
        else            { cpwait<0>(); }
        __syncthreads();

        const uint32_t ksh = smb + (st * 2) * 4608 * 2;
        const uint32_t vth = smb + (st * 2 + 1) * 4608 * 2;

        float S[8][4];
#pragma unroll
        for (int j = 0; j < 8; j++)
#pragma unroll
            for (int i = 0; i < 4; i++) S[j][i] = 0.f;
#pragma unroll
        for (int kk = 0; kk < 4; kk++) {
            const int cc = kk * 16 + lcol;
#pragma unroll
            for (int jp = 0; jp < 4; jp++) {
                const int br = jp * 16 + lrow;
                unsigned bh_[4];
                ldsm4(bh_[0], bh_[1], bh_[2], bh_[3], ksh + (br * 72 + cc) * 2);
                mma16(S[2*jp],     qh[kk], bh_[0], bh_[1]);
                mma16(S[2*jp + 1], qh[kk], bh_[2], bh_[3]);
            }
        }

        const bool edge = (kt == ktLast);
        float tm0 = -1e30f, tm1 = -1e30f;
#pragma unroll
        for (int j = 0; j < 8; j++) {
            const int kc0 = k0 + j * 8 + 2 * t4;
            const float c0 = -slope2 * (float)kc0;
            const float c1 = c0 - slope2;
            S[j][0] += c0;
            S[j][1] += c1;
            S[j][2] += c0;
            S[j][3] += c1;
            if (edge) {
                if (kc0 > r0)         S[j][0] = -1e30f;
                if (kc0 + 1 > r0)     S[j][1] = -1e30f;
                if (kc0 > r0 + 8)     S[j][2] = -1e30f;
                if (kc0 + 1 > r0 + 8) S[j][3] = -1e30f;
            }
            tm0 = fmaxf(tm0, fmaxf(S[j][0], S[j][1]));
            tm1 = fmaxf(tm1, fmaxf(S[j][2], S[j][3]));
        }
        tm0 = fmaxf(tm0, __shfl_xor_sync(0xffffffffu, tm0, 1));
        tm0 = fmaxf(tm0, __shfl_xor_sync(0xffffffffu, tm0, 2));
        tm1 = fmaxf(tm1, __shfl_xor_sync(0xffffffffu, tm1, 1));
        tm1 = fmaxf(tm1, __shfl_xor_sync(0xffffffffu, tm1, 2));

        const float mn0 = fmaxf(mrow0, tm0);
        const float mn1 = fmaxf(mrow1, tm1);
        const float al0 = ex2(mrow0 - mn0);
        const float al1 = ex2(mrow1 - mn1);
        mrow0 = mn0; mrow1 = mn1;
#pragma unroll
        for (int i = 0; i < 8; i++) {
            Oacc[i][0] *= al0; Oacc[i][1] *= al0;
            Oacc[i][2] *= al1; Oacc[i][3] *= al1;
        }

        float Lacc[4] = {0.f, 0.f, 0.f, 0.f};
#pragma unroll
        for (int jj = 0; jj < 4; jj++) {
            unsigned ph[4];
            ph[0] = h2u(h2exp2(__floats2half2_rn(S[2*jj][0] - mn0, S[2*jj][1] - mn0)));
            ph[1] = h2u(h2exp2(__floats2half2_rn(S[2*jj][2] - mn1, S[2*jj][3] - mn1)));
            ph[2] = h2u(h2exp2(__floats2half2_rn(S[2*jj+1][0] - mn0, S[2*jj+1][1] - mn0)));
            ph[3] = h2u(h2exp2(__floats2half2_rn(S[2*jj+1][2] - mn1, S[2*jj+1][3] - mn1)));
            mma16(Lacc, ph, 0x3C003C00u, 0x3C003C00u);
            const int cc = jj * 16 + lcol;
#pragma unroll
            for (int dp = 0; dp < 4; dp++) {
                const int d0 = 2 * dp, d1 = d0 + 1;
                const int vr = dp * 16 + lrow;
                unsigned vh[4];
                ldsm4(vh[0], vh[1], vh[2], vh[3], vth + (vr * 72 + cc) * 2);
                mma16(Oacc[d0], ph, vh[0], vh[1]);
                mma16(Oacc[d1], ph, vh[2], vh[3]);
            }
        }
        lrow0f = lrow0f * al0 + Lacc[0];
        lrow1f = lrow1f * al1 + Lacc[2];
        __syncthreads();
    }

    const float inv0 = 1.f / lrow0f;
    const float inv1 = 1.f / lrow1f;
    __half* OhB = Ohi + (size_t)bh * SS * DD;
#pragma unroll
    for (int dn = 0; dn < 8; dn++) {
        const int col = dn * 8 + 2 * t4;
        *(unsigned*)(OhB + (size_t)r0 * DD + col) =
            h2u(__floats2half2_rn(Oacc[dn][0] * inv0, Oacc[dn][1] * inv0));
        *(unsigned*)(OhB + (size_t)(r0 + 8) * DD + col) =
            h2u(__floats2half2_rn(Oacc[dn][2] * inv1, Oacc[dn][3] * inv1));
    }
}

// ---------------------------------------------------------------------------
extern "C" void kernel_launch(void* const* d_in, const int* in_sizes, int n_in,
                              void* d_out, int out_size) {
    const float* x  = (const float*)d_in[0];
    const float* Wq = (const float*)d_in[1];
    const float* bq = (const float*)d_in[2];
    const float* Wk = (const float*)d_in[3];
    const float* bk = (const float*)d_in[4];
    const float* Wv = (const float*)d_in[5];
    const float* bv = (const float*)d_in[6];
    const float* Wo = (const float*)d_in[7];
    const float* bo = (const float*)d_in[8];
    float* out = (float*)d_out;

    __half *xhi, *wThi, *qhi, *khi, *vthi, *ohi;
    float* bqkv;
    cudaGetSymbolAddress((void**)&xhi, g_xhi);
    cudaGetSymbolAddress((void**)&wThi, g_wThi);
    cudaGetSymbolAddress((void**)&qhi, g_qhi);
    cudaGetSymbolAddress((void**)&khi, g_khi);
    cudaGetSymbolAddress((void**)&vthi, g_vthi);
    cudaGetSymbolAddress((void**)&ohi, g_ohi);
    cudaGetSymbolAddress((void**)&bqkv, g_bqkv);

    cudaFuncSetAttribute(gemm16<4>, cudaFuncAttributeMaxDynamicSharedMemorySize, SM_G);
    cudaFuncSetAttribute(gemm16<0>, cudaFuncAttributeMaxDynamicSharedMemorySize, SM_G);

    // prepass (hi-only everywhere)
    const int n4 = MM * EE / 4;
    split_hi<<<(n4 + 255) / 256, 256>>>(x, xhi, n4);
    dim3 wt4(24, 24, 4);
    split_wT4<<<wt4, 256>>>(Wq, Wk, Wv, Wo, wThi);
    pack_bias<<<(3 * EE + 255) / 256, 256>>>(bq, bk, bv, bqkv);

    // Q + K + V fused, hi-only
    dim3 gqkv(MM / 128, EE / 128, 3);   // 64 x 6 x 3
    gemm16<4><<<gqkv, 512, SM_G>>>(xhi, wThi, bqkv, nullptr, qhi, khi, vthi);

    dim3 ga(SS / 64, BB * HH);          // 32 x 48
    attn16<<<ga, 128>>>(qhi, khi, vthi, ohi);

    // [B,H,S,D] flat == [B*S, E]; out = Ohi @ Wo_hi + bo
    dim3 gg(MM / 128, EE / 128);        // 64 x 6
    gemm16<0><<<gg, 512, SM_G>>>(ohi, wThi + 3 * (size_t)EE * EE, bo, out,
                                 nullptr, nullptr, nullptr);
}

// round 16
// speedup vs baseline: 1.8085x; 1.1163x over previous
#include <cuda_runtime.h>
#include <cuda_fp16.h>
#include <cstdint>
#include <cstddef>

#define BB 4
#define HH 12
#define SS 2048
#define DD 64
#define EE 768
#define MM (BB*SS)
#define NT (BB*HH*SS*DD)   // 6291456

// ---------------- scratch (__device__ globals; no allocation) --------------
__device__ __half g_xhi[MM*EE];
__device__ __half g_wThi[4*EE*EE];
__device__ __half g_qhi[NT];
__device__ __half g_khi[NT];
__device__ __half g_vthi[NT];              // V transposed: [bh][d][s]
__device__ __half g_ohi[NT];
__device__ float  g_bqkv[3*EE];

#define LOG2E 1.4426950408889634f

__constant__ float c_slopes[HH] = {
    0.6299605249f, 0.396850263f, 0.25f, 0.1574901312f,
    0.0992125657f, 0.0625f, 0.0393725328f, 0.0248031414f,
    0.015625f, 0.0098431332f, 0.0062007854f, 0.00390625f};

// ---------------------------------------------------------------------------
__device__ __forceinline__ uint32_t smem_u32(const void* p) {
    uint32_t a;
    asm("{ .reg .u64 t; cvta.to.shared.u64 t, %1; cvt.u32.u64 %0, t; }"
        : "=r"(a) : "l"(p));
    return a;
}
__device__ __forceinline__ unsigned h2u(__half2 h) {
    return reinterpret_cast<unsigned&>(h);
}
__device__ __forceinline__ float ex2(float x) {
    float y;
    asm("ex2.approx.f32 %0, %1;" : "=f"(y) : "f"(x));
    return y;
}
__device__ __forceinline__ void mma16(float* d, const unsigned* a,
                                      unsigned b0, unsigned b1) {
    asm volatile(
        "mma.sync.aligned.m16n8k16.row.col.f32.f16.f16.f32 "
        "{%0,%1,%2,%3}, {%4,%5,%6,%7}, {%8,%9}, {%0,%1,%2,%3};"
        : "+f"(d[0]), "+f"(d[1]), "+f"(d[2]), "+f"(d[3])
        : "r"(a[0]), "r"(a[1]), "r"(a[2]), "r"(a[3]), "r"(b0), "r"(b1));
}
__device__ __forceinline__ void ldsm4(unsigned& r0, unsigned& r1,
                                      unsigned& r2, unsigned& r3, uint32_t a) {
    asm volatile("ldmatrix.sync.aligned.m8n8.x4.shared.b16 {%0,%1,%2,%3}, [%4];"
                 : "=r"(r0), "=r"(r1), "=r"(r2), "=r"(r3) : "r"(a));
}
__device__ __forceinline__ void cpa16(uint32_t dst, const void* src) {
    asm volatile("cp.async.cg.shared.global [%0], [%1], 16;"
                 :: "r"(dst), "l"(src));
}
__device__ __forceinline__ void cpcommit() {
    asm volatile("cp.async.commit_group;" ::: "memory");
}
template <int N>
__device__ __forceinline__ void cpwait() {
    asm volatile("cp.async.wait_group %0;" :: "n"(N) : "memory");
}

// ---------------------------------------------------------------------------
// prepass
// ---------------------------------------------------------------------------
__global__ void __launch_bounds__(256)
split_hi(const float* __restrict__ in, __half* __restrict__ hi, int n4) {
    int i = blockIdx.x * 256 + threadIdx.x;
    if (i >= n4) return;
    float4 f = ((const float4*)in)[i];
    ((__half2*)hi)[2*i]   = __floats2half2_rn(f.x, f.y);
    ((__half2*)hi)[2*i+1] = __floats2half2_rn(f.z, f.w);
}

__global__ void __launch_bounds__(256)
split_wT4(const float* __restrict__ W0, const float* __restrict__ W1,
          const float* __restrict__ W2, const float* __restrict__ W3,
          __half* __restrict__ hiT) {
    __shared__ float t[32][33];
    const int z = blockIdx.z;
    const float* W = z == 0 ? W0 : (z == 1 ? W1 : (z == 2 ? W2 : W3));
    __half* hT = hiT + (size_t)z * EE * EE;
    const int r0 = blockIdx.y * 32, c0 = blockIdx.x * 32;
    const int tx = threadIdx.x & 31, ty = threadIdx.x >> 5;   // 32 x 8
#pragma unroll
    for (int j = 0; j < 4; j++)
        t[ty + 8*j][tx] = W[(size_t)(r0 + ty + 8*j) * EE + c0 + tx];
    __syncthreads();
#pragma unroll
    for (int j = 0; j < 4; j++)
        hT[(size_t)(c0 + ty + 8*j) * EE + r0 + tx] = __float2half_rn(t[tx][ty + 8*j]);
}

__global__ void __launch_bounds__(256)
pack_bias(const float* __restrict__ bq, const float* __restrict__ bk,
          const float* __restrict__ bv, float* __restrict__ dst) {
    int i = blockIdx.x * 256 + threadIdx.x;
    if (i < EE)            dst[i] = bq[i];
    else if (i < 2 * EE)   dst[i] = bk[i - EE];
    else if (i < 3 * EE)   dst[i] = bv[i - 2 * EE];
}

// ---------------------------------------------------------------------------
// fp16 GEMM v6: CTA tile 128x128, 4 warps (2x2, warp tile 64x64), 128 thr,
// BK=32, 2-stage cp.async, hi*hi single stream.
// 8 LDSM feed 32 MMAs per kk -> half the smem read traffic of the 4x4 grid.
// MODE 0: float out + bias. MODE 4: QKV fused (z: 0=Q scale,1=K,2=V transp).
// ---------------------------------------------------------------------------
#define SM_G 40960   // 2 stages x (A + B) x 5120 halfs x 2B

template <int MODE>
__global__ void __launch_bounds__(128, 2)
gemm16(const __half* __restrict__ Ah,
       const __half* __restrict__ BhBase,
       const float* __restrict__ biasBase, float* __restrict__ outf,
       __half* __restrict__ oq, __half* __restrict__ ok,
       __half* __restrict__ ov) {
    extern __shared__ __half sm[];
    const int SSTRIDE = 10240;

    const int tid  = threadIdx.x;
    const int lane = tid & 31;
    const int warp = tid >> 5;              // 0..3
    const int wm   = (warp >> 1) * 64;      // 0 or 64
    const int wn   = (warp & 1) * 64;       // 0 or 64
    const int m0   = blockIdx.x * 128;
    const int n0   = blockIdx.y * 128;
    const int z    = (MODE == 4) ? blockIdx.z : 0;
    const uint32_t smb = smem_u32(sm);

    const __half* Bh = (MODE == 4) ? BhBase + (size_t)z * EE * EE : BhBase;
    const float*  bias = (MODE == 4) ? biasBase + z * EE : biasBase;

    const int lrow = (lane & 7) + ((lane & 16) >> 1);
    const int lcol = (lane & 8);

    float acc[4][8][4];
#pragma unroll
    for (int mf = 0; mf < 4; mf++)
#pragma unroll
        for (int nf = 0; nf < 8; nf++)
#pragma unroll
            for (int i = 0; i < 4; i++) acc[mf][nf][i] = 0.f;

    auto load_stage = [&](int st, int k0) {
#pragma unroll
        for (int i = 0; i < 8; i++) {
            const int u = tid + i * 128;       // 0..1023: A then B
            const int t = u >> 9;
            const int w = u & 511;
            const int row = w >> 2, c8 = (w & 3) * 8;
            const __half* src = t ? Bh + (size_t)(n0 + row) * EE + k0 + c8
                                  : Ah + (size_t)(m0 + row) * EE + k0 + c8;
            const uint32_t dsth = st * SSTRIDE + t * 5120 + row * 40 + c8;
            cpa16(smb + dsth * 2, src);
        }
        cpcommit();
    };

    load_stage(0, 0);
    const int NC = EE / 32;   // 24
    for (int c = 0; c < NC; c++) {
        const int st = c & 1;
        if (c + 1 < NC) { load_stage(st ^ 1, (c + 1) * 32); cpwait<1>(); }
        else            { cpwait<0>(); }
        __syncthreads();

        const uint32_t aH = smb + (st * SSTRIDE) * 2;
        const uint32_t bH = smb + (st * SSTRIDE + 5120) * 2;

#pragma unroll
        for (int kk = 0; kk < 2; kk++) {
            const int cc = kk * 16;
            unsigned a_h[4][4];
#pragma unroll
            for (int mf = 0; mf < 4; mf++) {
                const int ar = wm + mf * 16 + (lane & 15);
                const int ac = cc + ((lane & 16) >> 1);
                ldsm4(a_h[mf][0], a_h[mf][1], a_h[mf][2], a_h[mf][3],
                      aH + (ar * 40 + ac) * 2);
            }
#pragma unroll
            for (int p = 0; p < 4; p++) {
                const int br = wn + p * 16 + lrow;
                const int bc = cc + lcol;
                unsigned bh[4];
                ldsm4(bh[0], bh[1], bh[2], bh[3], bH + (br * 40 + bc) * 2);
#pragma unroll
                for (int q = 0; q < 2; q++) {
                    const int nf = 2 * p + q;
                    mma16(acc[0][nf], a_h[0], bh[2*q], bh[2*q+1]);
                    mma16(acc[1][nf], a_h[1], bh[2*q], bh[2*q+1]);
                    mma16(acc[2][nf], a_h[2], bh[2*q], bh[2*q+1]);
                    mma16(acc[3][nf], a_h[3], bh[2*q], bh[2*q+1]);
                }
            }
        }
        __syncthreads();
    }

    const int g  = lane >> 2;
    const int t4 = lane & 3;
#pragma unroll
    for (int nf = 0; nf < 8; nf++) {
        const int nl = wn + nf * 8 + 2 * t4;
        const int n  = n0 + nl;
        const int hh_ = n >> 6;
        const int dl  = nl & 63;
        const float b0 = bias[n], b1 = bias[n + 1];
#pragma unroll
        for (int mf = 0; mf < 4; mf++) {
            const int m_lo = m0 + wm + mf * 16 + g;
            const int m_hi = m_lo + 8;
            float v0 = acc[mf][nf][0] + b0, v1 = acc[mf][nf][1] + b1;
            float v2 = acc[mf][nf][2] + b0, v3 = acc[mf][nf][3] + b1;
            if (MODE == 0) {
                *(float2*)(outf + (size_t)m_lo * EE + n) = make_float2(v0, v1);
                *(float2*)(outf + (size_t)m_hi * EE + n) = make_float2(v2, v3);
            } else {
                const int b_lo = m_lo >> 11, s_lo = m_lo & (SS - 1);
                const int b_hi = m_hi >> 11, s_hi = m_hi & (SS - 1);
                if (z == 2) {          // V -> [bh][d][s]
                    const size_t base_lo = ((size_t)(b_lo * HH + hh_)) * DD * SS;
                    const size_t base_hi = ((size_t)(b_hi * HH + hh_)) * DD * SS;
                    float vs[4] = {v0, v1, v2, v3};
#pragma unroll
                    for (int e = 0; e < 4; e++) {
                        const int d = dl + (e & 1);
                        const size_t o = (e < 2 ? base_lo : base_hi) +
                                         (size_t)d * SS + (e < 2 ? s_lo : s_hi);
                        ov[o] = __float2half_rn(vs[e]);
                    }
                } else {
                    __half* dst = (z == 0) ? oq : ok;
                    if (z == 0) {
                        const float qs = 0.125f * LOG2E;
                        v0 *= qs; v1 *= qs; v2 *= qs; v3 *= qs;
                    }
                    size_t o_lo = (((size_t)(b_lo * HH + hh_)) * SS + s_lo) * DD + dl;
                    size_t o_hi = (((size_t)(b_hi * HH + hh_)) * SS + s_hi) * DD + dl;
                    *(unsigned*)(dst + o_lo) = h2u(__floats2half2_rn(v0, v1));
                    *(unsigned*)(dst + o_hi) = h2u(__floats2half2_rn(v2, v3));
                }
            }
        }
    }
}

// ---------------------------------------------------------------------------
// Flash attention (proven R10 shape); window 33 log2-units; O fp16 hi.
// ---------------------------------------------------------------------------
__global__ void __launch_bounds__(128)
attn16(const __half* __restrict__ Qh, const __half* __restrict__ Kh,
       const __half* __restrict__ Vth, __half* __restrict__ Ohi) {
    __shared__ __half kv[2][2][64*72];

    const int tid  = threadIdx.x;
    const int lane = tid & 31;
    const int warp = tid >> 5;
    const int g    = lane >> 2;
    const int t4   = lane & 3;
    const uint32_t smb = smem_u32(kv);

    const int lrow = (lane & 7) + ((lane & 16) >> 1);
    const int lcol = (lane & 8);

    const int bh = blockIdx.y;
    const int h  = bh % HH;
    const int q0 = blockIdx.x * 64;
    const float slope2 = c_slopes[h] * LOG2E;

    const __half* Qhb = Qh + (size_t)bh * SS * DD;
    const __half* Khb = Kh + (size_t)bh * SS * DD;
    const __half* Vhb = Vth + (size_t)bh * DD * SS;

    const int r0 = q0 + warp * 16 + g;

    unsigned qh[4][4];
#pragma unroll
    for (int kk = 0; kk < 4; kk++) {
        const int c = kk * 16 + 2 * t4;
        qh[kk][0] = *(const unsigned*)(Qhb + (size_t)r0 * DD + c);
        qh[kk][1] = *(const unsigned*)(Qhb + (size_t)(r0 + 8) * DD + c);
        qh[kk][2] = *(const unsigned*)(Qhb + (size_t)r0 * DD + c + 8);
        qh[kk][3] = *(const unsigned*)(Qhb + (size_t)(r0 + 8) * DD + c + 8);
    }

    float Oacc[8][4];
#pragma unroll
    for (int i = 0; i < 8; i++)
#pragma unroll
        for (int j = 0; j < 4; j++) Oacc[i][j] = 0.f;
    float mrow0 = -1e30f, mrow1 = -1e30f, lrow0f = 0.f, lrow1f = 0.f;

    const int ktLast = q0 >> 6;
    int ktEnd = ktLast;
    {
        const int ctile = ((int)(33.f / slope2)) >> 6;
        if (ctile < ktEnd) ktEnd = ctile;
    }

    auto load_kv = [&](int st, int k0) {
#pragma unroll
        for (int i = 0; i < 8; i++) {
            const int u = tid + i * 128;
            const int t = u >> 9;
            const int w = u & 511;
            const int r = w >> 3, c8 = (w & 7) * 8;
            const __half* src = t ? (Vhb + (size_t)r * SS + k0 + c8)
                                  : (Khb + (size_t)(k0 + r) * DD + c8);
            const uint32_t dst = smb + (((st * 2 + t) * 4608) + r * 72 + c8) * 2;
            cpa16(dst, src);
        }
        cpcommit();
    };

    load_kv(0, 0);
    for (int kt = 0; kt <= ktEnd; kt++) {
        const int k0 = kt * 64;
        const int st = kt & 1;
        if (kt < ktEnd) { load_kv(st ^ 1, k0 + 64); cpwait<1>(); }
        else            { cpwait<0>(); }
        __syncthreads();

        const uint32_t ksh = smb + (st * 2) * 4608 * 2;
        const uint32_t vth = smb + (st * 2 + 1) * 4608 * 2;

        float S[8][4];
#pragma unroll
        for (int j = 0; j < 8; j++)
#pragma unroll
            for (int i = 0; i < 4; i++) S[j][i] = 0.f;
#pragma unroll
        for (int kk = 0; kk < 4; kk++) {
            const int cc = kk * 16 + lcol;
#pragma unroll
            for (int jp = 0; jp < 4; jp++) {
                const int br = jp * 16 + lrow;
                unsigned bh_[4];
                ldsm4(bh_[0], bh_[1], bh_[2], bh_[3], ksh + (br * 72 + cc) * 2);
                mma16(S[2*jp],     qh[kk], bh_[0], bh_[1]);
                mma16(S[2*jp + 1], qh[kk], bh_[2], bh_[3]);
            }
        }

        const bool edge = (kt == ktLast);
        float tm0 = -1e30f, tm1 = -1e30f;
#pragma unroll
        for (int j = 0; j < 8; j++) {
            const int kc0 = k0 + j * 8 + 2 * t4;
            const float c0 = -slope2 * (float)kc0;
            const float c1 = c0 - slope2;
            S[j][0] += c0;
            S[j][1] += c1;
            S[j][2] += c0;
            S[j][3] += c1;
            if (edge) {
                if (kc0 > r0)         S[j][0] = -1e30f;
                if (kc0 + 1 > r0)     S[j][1] = -1e30f;
                if (kc0 > r0 + 8)     S[j][2] = -1e30f;
                if (kc0 + 1 > r0 + 8) S[j][3] = -1e30f;
            }
            tm0 = fmaxf(tm0, fmaxf(S[j][0], S[j][1]));
            tm1 = fmaxf(tm1, fmaxf(S[j][2], S[j][3]));
        }
        tm0 = fmaxf(tm0, __shfl_xor_sync(0xffffffffu, tm0, 1));
        tm0 = fmaxf(tm0, __shfl_xor_sync(0xffffffffu, tm0, 2));
        tm1 = fmaxf(tm1, __shfl_xor_sync(0xffffffffu, tm1, 1));
        tm1 = fmaxf(tm1, __shfl_xor_sync(0xffffffffu, tm1, 2));

        const float mn0 = fmaxf(mrow0, tm0);
        const float mn1 = fmaxf(mrow1, tm1);
        const float al0 = ex2(mrow0 - mn0);
        const float al1 = ex2(mrow1 - mn1);
        mrow0 = mn0; mrow1 = mn1;
#pragma unroll
        for (int i = 0; i < 8; i++) {
            Oacc[i][0] *= al0; Oacc[i][1] *= al0;
            Oacc[i][2] *= al1; Oacc[i][3] *= al1;
        }

        float Lacc[4] = {0.f, 0.f, 0.f, 0.f};
#pragma unroll
        for (int jj = 0; jj < 4; jj++) {
            unsigned ph[4];
            ph[0] = h2u(h2exp2(__floats2half2_rn(S[2*jj][0] - mn0, S[2*jj][1] - mn0)));
            ph[1] = h2u(h2exp2(__floats2half2_rn(S[2*jj][2] - mn1, S[2*jj][3] - mn1)));
            ph[2] = h2u(h2exp2(__floats2half2_rn(S[2*jj+1][0] - mn0, S[2*jj+1][1] - mn0)));
            ph[3] = h2u(h2exp2(__floats2half2_rn(S[2*jj+1][2] - mn1, S[2*jj+1][3] - mn1)));
            mma16(Lacc, ph, 0x3C003C00u, 0x3C003C00u);
            const int cc = jj * 16 + lcol;
#pragma unroll
            for (int dp = 0; dp < 4; dp++) {
                const int d0 = 2 * dp, d1 = d0 + 1;
                const int vr = dp * 16 + lrow;
                unsigned vh[4];
                ldsm4(vh[0], vh[1], vh[2], vh[3], vth + (vr * 72 + cc) * 2);
                mma16(Oacc[d0], ph, vh[0], vh[1]);
                mma16(Oacc[d1], ph, vh[2], vh[3]);
            }
        }
        lrow0f = lrow0f * al0 + Lacc[0];
        lrow1f = lrow1f * al1 + Lacc[2];
        __syncthreads();
    }

    const float inv0 = 1.f / lrow0f;
    const float inv1 = 1.f / lrow1f;
    __half* OhB = Ohi + (size_t)bh * SS * DD;
#pragma unroll
    for (int dn = 0; dn < 8; dn++) {
        const int col = dn * 8 + 2 * t4;
        *(unsigned*)(OhB + (size_t)r0 * DD + col) =
            h2u(__floats2half2_rn(Oacc[dn][0] * inv0, Oacc[dn][1] * inv0));
        *(unsigned*)(OhB + (size_t)(r0 + 8) * DD + col) =
            h2u(__floats2half2_rn(Oacc[dn][2] * inv1, Oacc[dn][3] * inv1));
    }
}

// ---------------------------------------------------------------------------
extern "C" void kernel_launch(void* const* d_in, const int* in_sizes, int n_in,
                              void* d_out, int out_size) {
    const float* x  = (const float*)d_in[0];
    const float* Wq = (const float*)d_in[1];
    const float* bq = (const float*)d_in[2];
    const float* Wk = (const float*)d_in[3];
    const float* bk = (const float*)d_in[4];
    const float* Wv = (const float*)d_in[5];
    const float* bv = (const float*)d_in[6];
    const float* Wo = (const float*)d_in[7];
    const float* bo = (const float*)d_in[8];
    float* out = (float*)d_out;

    __half *xhi, *wThi, *qhi, *khi, *vthi, *ohi;
    float* bqkv;
    cudaGetSymbolAddress((void**)&xhi, g_xhi);
    cudaGetSymbolAddress((void**)&wThi, g_wThi);
    cudaGetSymbolAddress((void**)&qhi, g_qhi);
    cudaGetSymbolAddress((void**)&khi, g_khi);
    cudaGetSymbolAddress((void**)&vthi, g_vthi);
    cudaGetSymbolAddress((void**)&ohi, g_ohi);
    cudaGetSymbolAddress((void**)&bqkv, g_bqkv);

    cudaFuncSetAttribute(gemm16<4>, cudaFuncAttributeMaxDynamicSharedMemorySize, SM_G);
    cudaFuncSetAttribute(gemm16<0>, cudaFuncAttributeMaxDynamicSharedMemorySize, SM_G);

    // prepass (hi-only everywhere)
    const int n4 = MM * EE / 4;
    split_hi<<<(n4 + 255) / 256, 256>>>(x, xhi, n4);
    dim3 wt4(24, 24, 4);
    split_wT4<<<wt4, 256>>>(Wq, Wk, Wv, Wo, wThi);
    pack_bias<<<(3 * EE + 255) / 256, 256>>>(bq, bk, bv, bqkv);

    // Q + K + V fused, hi-only
    dim3 gqkv(MM / 128, EE / 128, 3);   // 64 x 6 x 3
    gemm16<4><<<gqkv, 128, SM_G>>>(xhi, wThi, bqkv, nullptr, qhi, khi, vthi);

    dim3 ga(SS / 64, BB * HH);          // 32 x 48
    attn16<<<ga, 128>>>(qhi, khi, vthi, ohi);

    // [B,H,S,D] flat == [B*S, E]; out = Ohi @ Wo_hi + bo
    dim3 gg(MM / 128, EE / 128);        // 64 x 6
    gemm16<0><<<gg, 128, SM_G>>>(ohi, wThi + 3 * (size_t)EE * EE, bo, out,
                                 nullptr, nullptr, nullptr);
}

// round 17
// speedup vs baseline: 1.8129x; 1.0025x over previous
#include <cuda_runtime.h>
#include <cuda_fp16.h>
#include <cstdint>
#include <cstddef>

#define BB 4
#define HH 12
#define SS 2048
#define DD 64
#define EE 768
#define MM (BB*SS)
#define NT (BB*HH*SS*DD)   // 6291456

// ---------------- scratch (__device__ globals; no allocation) --------------
__device__ __half g_xhi[MM*EE];
__device__ __half g_wThi[4*EE*EE];
__device__ __half g_qhi[NT];
__device__ __half g_khi[NT];
__device__ __half g_vthi[NT];              // V transposed: [bh][d][s]
__device__ __half g_ohi[NT];
__device__ float  g_bqkv[3*EE];

#define LOG2E 1.4426950408889634f

__constant__ float c_slopes[HH] = {
    0.6299605249f, 0.396850263f, 0.25f, 0.1574901312f,
    0.0992125657f, 0.0625f, 0.0393725328f, 0.0248031414f,
    0.015625f, 0.0098431332f, 0.0062007854f, 0.00390625f};

// ---------------------------------------------------------------------------
__device__ __forceinline__ uint32_t smem_u32(const void* p) {
    uint32_t a;
    asm("{ .reg .u64 t; cvta.to.shared.u64 t, %1; cvt.u32.u64 %0, t; }"
        : "=r"(a) : "l"(p));
    return a;
}
__device__ __forceinline__ unsigned h2u(__half2 h) {
    return reinterpret_cast<unsigned&>(h);
}
__device__ __forceinline__ float ex2(float x) {
    float y;
    asm("ex2.approx.f32 %0, %1;" : "=f"(y) : "f"(x));
    return y;
}
__device__ __forceinline__ void mma16(float* d, const unsigned* a,
                                      unsigned b0, unsigned b1) {
    asm volatile(
        "mma.sync.aligned.m16n8k16.row.col.f32.f16.f16.f32 "
        "{%0,%1,%2,%3}, {%4,%5,%6,%7}, {%8,%9}, {%0,%1,%2,%3};"
        : "+f"(d[0]), "+f"(d[1]), "+f"(d[2]), "+f"(d[3])
        : "r"(a[0]), "r"(a[1]), "r"(a[2]), "r"(a[3]), "r"(b0), "r"(b1));
}
__device__ __forceinline__ void ldsm4(unsigned& r0, unsigned& r1,
                                      unsigned& r2, unsigned& r3, uint32_t a) {
    asm volatile("ldmatrix.sync.aligned.m8n8.x4.shared.b16 {%0,%1,%2,%3}, [%4];"
                 : "=r"(r0), "=r"(r1), "=r"(r2), "=r"(r3) : "r"(a));
}
__device__ __forceinline__ void cpa16(uint32_t dst, const void* src) {
    asm volatile("cp.async.cg.shared.global [%0], [%1], 16;"
                 :: "r"(dst), "l"(src));
}
__device__ __forceinline__ void cpcommit() {
    asm volatile("cp.async.commit_group;" ::: "memory");
}
template <int N>
__device__ __forceinline__ void cpwait() {
    asm volatile("cp.async.wait_group %0;" :: "n"(N) : "memory");
}

// ---------------------------------------------------------------------------
// prepass
// ---------------------------------------------------------------------------
__global__ void __launch_bounds__(256)
split_hi(const float* __restrict__ in, __half* __restrict__ hi, int n4) {
    int i = blockIdx.x * 256 + threadIdx.x;
    if (i >= n4) return;
    float4 f = ((const float4*)in)[i];
    ((__half2*)hi)[2*i]   = __floats2half2_rn(f.x, f.y);
    ((__half2*)hi)[2*i+1] = __floats2half2_rn(f.z, f.w);
}

__global__ void __launch_bounds__(256)
split_wT4(const float* __restrict__ W0, const float* __restrict__ W1,
          const float* __restrict__ W2, const float* __restrict__ W3,
          __half* __restrict__ hiT) {
    __shared__ float t[32][33];
    const int z = blockIdx.z;
    const float* W = z == 0 ? W0 : (z == 1 ? W1 : (z == 2 ? W2 : W3));
    __half* hT = hiT + (size_t)z * EE * EE;
    const int r0 = blockIdx.y * 32, c0 = blockIdx.x * 32;
    const int tx = threadIdx.x & 31, ty = threadIdx.x >> 5;   // 32 x 8
#pragma unroll
    for (int j = 0; j < 4; j++)
        t[ty + 8*j][tx] = W[(size_t)(r0 + ty + 8*j) * EE + c0 + tx];
    __syncthreads();
#pragma unroll
    for (int j = 0; j < 4; j++)
        hT[(size_t)(c0 + ty + 8*j) * EE + r0 + tx] = __float2half_rn(t[tx][ty + 8*j]);
}

__global__ void __launch_bounds__(256)
pack_bias(const float* __restrict__ bq, const float* __restrict__ bk,
          const float* __restrict__ bv, float* __restrict__ dst) {
    int i = blockIdx.x * 256 + threadIdx.x;
    if (i < EE)            dst[i] = bq[i];
    else if (i < 2 * EE)   dst[i] = bk[i - EE];
    else if (i < 3 * EE)   dst[i] = bv[i - 2 * EE];
}

// ---------------------------------------------------------------------------
// fp16 GEMM v7: CTA tile 128x128, 4 warps (2x2, warp tile 64x64), 128 thr,
// BK=64 (12 iterations), 2-stage cp.async, hi*hi single stream.
// Smem/stage (halfs): A 128x72 @0, B 128x72 @9216; stage stride 18432.
// Total 73728 B (2 CTAs/SM).
// MODE 0: float out + bias. MODE 4: QKV fused (z: 0=Q scale,1=K,2=V transp).
// ---------------------------------------------------------------------------
#define SM_G 73728

template <int MODE>
__global__ void __launch_bounds__(128, 2)
gemm16(const __half* __restrict__ Ah,
       const __half* __restrict__ BhBase,
       const float* __restrict__ biasBase, float* __restrict__ outf,
       __half* __restrict__ oq, __half* __restrict__ ok,
       __half* __restrict__ ov) {
    extern __shared__ __half sm[];
    const int SSTRIDE = 18432;

    const int tid  = threadIdx.x;
    const int lane = tid & 31;
    const int warp = tid >> 5;              // 0..3
    const int wm   = (warp >> 1) * 64;      // 0 or 64
    const int wn   = (warp & 1) * 64;       // 0 or 64
    const int m0   = blockIdx.x * 128;
    const int n0   = blockIdx.y * 128;
    const int z    = (MODE == 4) ? blockIdx.z : 0;
    const uint32_t smb = smem_u32(sm);

    const __half* Bh = (MODE == 4) ? BhBase + (size_t)z * EE * EE : BhBase;
    const float*  bias = (MODE == 4) ? biasBase + z * EE : biasBase;

    const int lrow = (lane & 7) + ((lane & 16) >> 1);
    const int lcol = (lane & 8);

    float acc[4][8][4];
#pragma unroll
    for (int mf = 0; mf < 4; mf++)
#pragma unroll
        for (int nf = 0; nf < 8; nf++)
#pragma unroll
            for (int i = 0; i < 4; i++) acc[mf][nf][i] = 0.f;

    auto load_stage = [&](int st, int k0) {
#pragma unroll
        for (int i = 0; i < 16; i++) {
            const int u = tid + i * 128;       // 0..2047: A(1024) then B(1024)
            const int t = u >> 10;
            const int w = u & 1023;
            const int row = w >> 3, c8 = (w & 7) * 8;
            const __half* src = t ? Bh + (size_t)(n0 + row) * EE + k0 + c8
                                  : Ah + (size_t)(m0 + row) * EE + k0 + c8;
            const uint32_t dsth = st * SSTRIDE + t * 9216 + row * 72 + c8;
            cpa16(smb + dsth * 2, src);
        }
        cpcommit();
    };

    load_stage(0, 0);
    const int NC = EE / 64;   // 12
    for (int c = 0; c < NC; c++) {
        const int st = c & 1;
        if (c + 1 < NC) { load_stage(st ^ 1, (c + 1) * 64); cpwait<1>(); }
        else            { cpwait<0>(); }
        __syncthreads();

        const uint32_t aH = smb + (st * SSTRIDE) * 2;
        const uint32_t bH = smb + (st * SSTRIDE + 9216) * 2;

#pragma unroll
        for (int kk = 0; kk < 4; kk++) {
            const int cc = kk * 16;
            unsigned a_h[4][4];
#pragma unroll
            for (int mf = 0; mf < 4; mf++) {
                const int ar = wm + mf * 16 + (lane & 15);
                const int ac = cc + ((lane & 16) >> 1);
                ldsm4(a_h[mf][0], a_h[mf][1], a_h[mf][2], a_h[mf][3],
                      aH + (ar * 72 + ac) * 2);
            }
#pragma unroll
            for (int p = 0; p < 4; p++) {
                const int br = wn + p * 16 + lrow;
                const int bc = cc + lcol;
                unsigned bh[4];
                ldsm4(bh[0], bh[1], bh[2], bh[3], bH + (br * 72 + bc) * 2);
#pragma unroll
                for (int q = 0; q < 2; q++) {
                    const int nf = 2 * p + q;
                    mma16(acc[0][nf], a_h[0], bh[2*q], bh[2*q+1]);
                    mma16(acc[1][nf], a_h[1], bh[2*q], bh[2*q+1]);
                    mma16(acc[2][nf], a_h[2], bh[2*q], bh[2*q+1]);
                    mma16(acc[3][nf], a_h[3], bh[2*q], bh[2*q+1]);
                }
            }
        }
        __syncthreads();
    }

    const int g  = lane >> 2;
    const int t4 = lane & 3;
#pragma unroll
    for (int nf = 0; nf < 8; nf++) {
        const int nl = wn + nf * 8 + 2 * t4;
        const int n  = n0 + nl;
        const int hh_ = n >> 6;
        const int dl  = nl & 63;
        const float b0 = bias[n], b1 = bias[n + 1];
#pragma unroll
        for (int mf = 0; mf < 4; mf++) {
            const int m_lo = m0 + wm + mf * 16 + g;
            const int m_hi = m_lo + 8;
            float v0 = acc[mf][nf][0] + b0, v1 = acc[mf][nf][1] + b1;
            float v2 = acc[mf][nf][2] + b0, v3 = acc[mf][nf][3] + b1;
            if (MODE == 0) {
                *(float2*)(outf + (size_t)m_lo * EE + n) = make_float2(v0, v1);
                *(float2*)(outf + (size_t)m_hi * EE + n) = make_float2(v2, v3);
            } else {
                const int b_lo = m_lo >> 11, s_lo = m_lo & (SS - 1);
                const int b_hi = m_hi >> 11, s_hi = m_hi & (SS - 1);
                if (z == 2) {          // V -> [bh][d][s]
                    const size_t base_lo = ((size_t)(b_lo * HH + hh_)) * DD * SS;
                    const size_t base_hi = ((size_t)(b_hi * HH + hh_)) * DD * SS;
                    float vs[4] = {v0, v1, v2, v3};
#pragma unroll
                    for (int e = 0; e < 4; e++) {
                        const int d = dl + (e & 1);
                        const size_t o = (e < 2 ? base_lo : base_hi) +
                                         (size_t)d * SS + (e < 2 ? s_lo : s_hi);
                        ov[o] = __float2half_rn(vs[e]);
                    }
                } else {
                    __half* dst = (z == 0) ? oq : ok;
                    if (z == 0) {
                        const float qs = 0.125f * LOG2E;
                        v0 *= qs; v1 *= qs; v2 *= qs; v3 *= qs;
                    }
                    size_t o_lo = (((size_t)(b_lo * HH + hh_)) * SS + s_lo) * DD + dl;
                    size_t o_hi = (((size_t)(b_hi * HH + hh_)) * SS + s_hi) * DD + dl;
                    *(unsigned*)(dst + o_lo) = h2u(__floats2half2_rn(v0, v1));
                    *(unsigned*)(dst + o_hi) = h2u(__floats2half2_rn(v2, v3));
                }
            }
        }
    }
}

// ---------------------------------------------------------------------------
// Flash attention (proven R10 shape); window 33 log2-units; O fp16 hi.
// ---------------------------------------------------------------------------
__global__ void __launch_bounds__(128)
attn16(const __half* __restrict__ Qh, const __half* __restrict__ Kh,
       const __half* __restrict__ Vth, __half* __restrict__ Ohi) {
    __shared__ __half kv[2][2][64*72];

    const int tid  = threadIdx.x;
    const int lane = tid & 31;
    const int warp = tid >> 5;
    const int g    = lane >> 2;
    const int t4   = lane & 3;
    const uint32_t smb = smem_u32(kv);

    const int lrow = (lane & 7) + ((lane & 16) >> 1);
    const int lcol = (lane & 8);

    const int bh = blockIdx.y;
    const int h  = bh % HH;
    const int q0 = blockIdx.x * 64;
    const float slope2 = c_slopes[h] * LOG2E;

    const __half* Qhb = Qh + (size_t)bh * SS * DD;
    const __half* Khb = Kh + (size_t)bh * SS * DD;
    const __half* Vhb = Vth + (size_t)bh * DD * SS;

    const int r0 = q0 + warp * 16 + g;

    unsigned qh[4][4];
#pragma unroll
    for (int kk = 0; kk < 4; kk++) {
        const int c = kk * 16 + 2 * t4;
        qh[kk][0] = *(const unsigned*)(Qhb + (size_t)r0 * DD + c);
        qh[kk][1] = *(const unsigned*)(Qhb + (size_t)(r0 + 8) * DD + c);
        qh[kk][2] = *(const unsigned*)(Qhb + (size_t)r0 * DD + c + 8);
        qh[kk][3] = *(const unsigned*)(Qhb + (size_t)(r0 + 8) * DD + c + 8);
    }

    float Oacc[8][4];
#pragma unroll
    for (int i = 0; i < 8; i++)
#pragma unroll
        for (int j = 0; j < 4; j++) Oacc[i][j] = 0.f;
    float mrow0 = -1e30f, mrow1 = -1e30f, lrow0f = 0.f, lrow1f = 0.f;

    const int ktLast = q0 >> 6;
    int ktEnd = ktLast;
    {
        const int ctile = ((int)(33.f / slope2)) >> 6;
        if (ctile < ktEnd) ktEnd = ctile;
    }

    auto load_kv = [&](int st, int k0) {
#pragma unroll
        for (int i = 0; i < 8; i++) {
            const int u = tid + i * 128;
            const int t = u >> 9;
            const int w = u & 511;
            const int r = w >> 3, c8 = (w & 7) * 8;
            const __half* src = t ? (Vhb + (size_t)r * SS + k0 + c8)
                                  : (Khb + (size_t)(k0 + r) * DD + c8);
            const uint32_t dst = smb + (((st * 2 + t) * 4608) + r * 72 + c8) * 2;
            cpa16(dst, src);
        }
        cpcommit();
    };

    load_kv(0, 0);
    for (int kt = 0; kt <= ktEnd; kt++) {
        const int k0 = kt * 64;
        const int st = kt & 1;
        if (kt < ktEnd) { load_kv(st ^ 1, k0 + 64); cpwait<1>(); }
        else            { cpwait<0>(); }
        __syncthreads();

        const uint32_t ksh = smb + (st * 2) * 4608 * 2;
        const uint32_t vth = smb + (st * 2 + 1) * 4608 * 2;

        float S[8][4];
#pragma unroll
        for (int j = 0; j < 8; j++)
#pragma unroll
            for (int i = 0; i < 4; i++) S[j][i] = 0.f;
#pragma unroll
        for (int kk = 0; kk < 4; kk++) {
            const int cc = kk * 16 + lcol;
#pragma unroll
            for (int jp = 0; jp < 4; jp++) {
                const int br = jp * 16 + lrow;
                unsigned bh_[4];
                ldsm4(bh_[0], bh_[1], bh_[2], bh_[3], ksh + (br * 72 + cc) * 2);
                mma16(S[2*jp],     qh[kk], bh_[0], bh_[1]);
                mma16(S[2*jp + 1], qh[kk], bh_[2], bh_[3]);
            }
        }

        const bool edge = (kt == ktLast);
        float tm0 = -1e30f, tm1 = -1e30f;
#pragma unroll
        for (int j = 0; j < 8; j++) {
            const int kc0 = k0 + j * 8 + 2 * t4;
            const float c0 = -slope2 * (float)kc0;
            const float c1 = c0 - slope2;
            S[j][0] += c0;
            S[j][1] += c1;
            S[j][2] += c0;
            S[j][3] += c1;
            if (edge) {
                if (kc0 > r0)         S[j][0] = -1e30f;
                if (kc0 + 1 > r0)     S[j][1] = -1e30f;
                if (kc0 > r0 + 8)     S[j][2] = -1e30f;
                if (kc0 + 1 > r0 + 8) S[j][3] = -1e30f;
            }
            tm0 = fmaxf(tm0, fmaxf(S[j][0], S[j][1]));
            tm1 = fmaxf(tm1, fmaxf(S[j][2], S[j][3]));
        }
        tm0 = fmaxf(tm0, __shfl_xor_sync(0xffffffffu, tm0, 1));
        tm0 = fmaxf(tm0, __shfl_xor_sync(0xffffffffu, tm0, 2));
        tm1 = fmaxf(tm1, __shfl_xor_sync(0xffffffffu, tm1, 1));
        tm1 = fmaxf(tm1, __shfl_xor_sync(0xffffffffu, tm1, 2));

        const float mn0 = fmaxf(mrow0, tm0);
        const float mn1 = fmaxf(mrow1, tm1);
        const float al0 = ex2(mrow0 - mn0);
        const float al1 = ex2(mrow1 - mn1);
        mrow0 = mn0; mrow1 = mn1;
#pragma unroll
        for (int i = 0; i < 8; i++) {
            Oacc[i][0] *= al0; Oacc[i][1] *= al0;
            Oacc[i][2] *= al1; Oacc[i][3] *= al1;
        }

        float Lacc[4] = {0.f, 0.f, 0.f, 0.f};
#pragma unroll
        for (int jj = 0; jj < 4; jj++) {
            unsigned ph[4];
            ph[0] = h2u(h2exp2(__floats2half2_rn(S[2*jj][0] - mn0, S[2*jj][1] - mn0)));
            ph[1] = h2u(h2exp2(__floats2half2_rn(S[2*jj][2] - mn1, S[2*jj][3] - mn1)));
            ph[2] = h2u(h2exp2(__floats2half2_rn(S[2*jj+1][0] - mn0, S[2*jj+1][1] - mn0)));
            ph[3] = h2u(h2exp2(__floats2half2_rn(S[2*jj+1][2] - mn1, S[2*jj+1][3] - mn1)));
            mma16(Lacc, ph, 0x3C003C00u, 0x3C003C00u);
            const int cc = jj * 16 + lcol;
#pragma unroll
            for (int dp = 0; dp < 4; dp++) {
                const int d0 = 2 * dp, d1 = d0 + 1;
                const int vr = dp * 16 + lrow;
                unsigned vh[4];
                ldsm4(vh[0], vh[1], vh[2], vh[3], vth + (vr * 72 + cc) * 2);
                mma16(Oacc[d0], ph, vh[0], vh[1]);
                mma16(Oacc[d1], ph, vh[2], vh[3]);
            }
        }
        lrow0f = lrow0f * al0 + Lacc[0];
        lrow1f = lrow1f * al1 + Lacc[2];
        __syncthreads();
    }

    const float inv0 = 1.f / lrow0f;
    const float inv1 = 1.f / lrow1f;
    __half* OhB = Ohi + (size_t)bh * SS * DD;
#pragma unroll
    for (int dn = 0; dn < 8; dn++) {
        const int col = dn * 8 + 2 * t4;
        *(unsigned*)(OhB + (size_t)r0 * DD + col) =
            h2u(__floats2half2_rn(Oacc[dn][0] * inv0, Oacc[dn][1] * inv0));
        *(unsigned*)(OhB + (size_t)(r0 + 8) * DD + col) =
            h2u(__floats2half2_rn(Oacc[dn][2] * inv1, Oacc[dn][3] * inv1));
    }
}

// ---------------------------------------------------------------------------
extern "C" void kernel_launch(void* const* d_in, const int* in_sizes, int n_in,
                              void* d_out, int out_size) {
    const float* x  = (const float*)d_in[0];
    const float* Wq = (const float*)d_in[1];
    const float* bq = (const float*)d_in[2];
    const float* Wk = (const float*)d_in[3];
    const float* bk = (const float*)d_in[4];
    const float* Wv = (const float*)d_in[5];
    const float* bv = (const float*)d_in[6];
    const float* Wo = (const float*)d_in[7];
    const float* bo = (const float*)d_in[8];
    float* out = (float*)d_out;

    __half *xhi, *wThi, *qhi, *khi, *vthi, *ohi;
    float* bqkv;
    cudaGetSymbolAddress((void**)&xhi, g_xhi);
    cudaGetSymbolAddress((void**)&wThi, g_wThi);
    cudaGetSymbolAddress((void**)&qhi, g_qhi);
    cudaGetSymbolAddress((void**)&khi, g_khi);
    cudaGetSymbolAddress((void**)&vthi, g_vthi);
    cudaGetSymbolAddress((void**)&ohi, g_ohi);
    cudaGetSymbolAddress((void**)&bqkv, g_bqkv);

    cudaFuncSetAttribute(gemm16<4>, cudaFuncAttributeMaxDynamicSharedMemorySize, SM_G);
    cudaFuncSetAttribute(gemm16<0>, cudaFuncAttributeMaxDynamicSharedMemorySize, SM_G);

    // prepass (hi-only everywhere)
    const int n4 = MM * EE / 4;
    split_hi<<<(n4 + 255) / 256, 256>>>(x, xhi, n4);
    dim3 wt4(24, 24, 4);
    split_wT4<<<wt4, 256>>>(Wq, Wk, Wv, Wo, wThi);
    pack_bias<<<(3 * EE + 255) / 256, 256>>>(bq, bk, bv, bqkv);

    // Q + K + V fused, hi-only
    dim3 gqkv(MM / 128, EE / 128, 3);   // 64 x 6 x 3
    gemm16<4><<<gqkv, 128, SM_G>>>(xhi, wThi, bqkv, nullptr, qhi, khi, vthi);

    dim3 ga(SS / 64, BB * HH);          // 32 x 48
    attn16<<<ga, 128>>>(qhi, khi, vthi, ohi);

    // [B,H,S,D] flat == [B*S, E]; out = Ohi @ Wo_hi + bo
    dim3 gg(MM / 128, EE / 128);        // 64 x 6
    gemm16<0><<<gg, 128, SM_G>>>(ohi, wThi + 3 * (size_t)EE * EE, bo, out,
                                 nullptr, nullptr, nullptr);
}